// round 4
// baseline (speedup 1.0000x reference)
#include <cuda_runtime.h>

#define BB 256
#define DD 564
#define SS 40
#define PP 20
#define NBL 6
#define NCOL 2256      /* 4*DD */
#define ROWS 10240     /* BB*SS */
#define OUTIN 1128

// ---------------- scratch (static device globals; no allocation) ----------------
__device__ float g_x[ROWS * DD];          // activations (b,s,d)  23.1 MB
__device__ float g_h[ROWS * DD];          // layernorm output     23.1 MB
__device__ float g_pre[SS * BB * NCOL];   // (s,b,g*D+e)          92.4 MB
__device__ float g_c[BB * DD];
__device__ float g_nrm[BB * DD];
__device__ float g_m[BB * DD];
__device__ float g_hsbuf[2][BB * DD];     // double-buffered hidden state
__device__ float g_mean[DD];
__device__ float g_rstd[DD];

// ---------------- input reshape: inp(b, d*S+s) -> x(b,s,d) ----------------
__global__ void k_reshape(const float* __restrict__ inp) {
    int idx = blockIdx.x * blockDim.x + threadIdx.x;
    if (idx >= ROWS * DD) return;
    int d = idx % DD;
    int r = idx / DD;
    int s = r % SS;
    int b = r / SS;
    g_x[idx] = inp[(size_t)b * (DD * SS) + d * SS + s];
}

__global__ void k_zero_state() {
    int idx = blockIdx.x * blockDim.x + threadIdx.x;
    if (idx < BB * DD) {
        g_c[idx] = 0.f; g_nrm[idx] = 0.f; g_m[idx] = 0.f;
        g_hsbuf[0][idx] = 0.f; g_hsbuf[1][idx] = 0.f;
    }
}

// ---------------- per-row layernorm over D ----------------
__global__ void k_layernorm(const float* __restrict__ lng, const float* __restrict__ lnb) {
    int row = blockIdx.x;
    const float* xr = g_x + (size_t)row * DD;
    __shared__ float red[128];
    __shared__ float s_mu, s_rs;
    float s1 = 0.f, s2 = 0.f;
    for (int d = threadIdx.x; d < DD; d += 128) { float v = xr[d]; s1 += v; s2 += v * v; }
    red[threadIdx.x] = s1; __syncthreads();
    for (int o = 64; o > 0; o >>= 1) { if (threadIdx.x < o) red[threadIdx.x] += red[threadIdx.x + o]; __syncthreads(); }
    if (threadIdx.x == 0) s_mu = red[0] / DD;
    __syncthreads();
    red[threadIdx.x] = s2; __syncthreads();
    for (int o = 64; o > 0; o >>= 1) { if (threadIdx.x < o) red[threadIdx.x] += red[threadIdx.x + o]; __syncthreads(); }
    if (threadIdx.x == 0) {
        float var = red[0] / DD - s_mu * s_mu;
        s_rs = rsqrtf(var + 1e-5f);
    }
    __syncthreads();
    float mu = s_mu, rs = s_rs;
    for (int d = threadIdx.x; d < DD; d += 128)
        g_h[(size_t)row * DD + d] = (xr[d] - mu) * rs * lng[d] + lnb[d];
}

// ---------------- W GEMM: pre[s,b,g*D+e] = h(b,s,:) @ W[g] + bias[g] ----------------
// 128x128x8 tile, 256 threads, 8x8 microtile.  grid (5, 80, 4)
__global__ void __launch_bounds__(256) k_wgemm(const float* __restrict__ W,
                                               const float* __restrict__ bias) {
    const int TM = 128, TN = 128, TK = 8;
    int g  = blockIdx.z;
    int n0 = blockIdx.x * TN;
    int m0 = blockIdx.y * TM;
    const float* Wg = W + (size_t)g * DD * DD;
    const float* bgp = bias + g * DD;
    __shared__ float As[TK][TM];
    __shared__ float Bs[TK][TN];
    int t = threadIdx.x;
    int ty = t >> 4, tx = t & 15;
    float acc[8][8];
#pragma unroll
    for (int i = 0; i < 8; i++)
#pragma unroll
        for (int j = 0; j < 8; j++) acc[i][j] = 0.f;

    int arow = t >> 1;          // 0..127
    int akk  = (t & 1) * 4;     // 0 or 4
    int bkk  = t >> 5;          // 0..7
    int bcol = (t & 31) * 4;    // 0..124

    for (int k0 = 0; k0 < DD; k0 += TK) {
        { // A tile (transposed into As[k][m])
            int gk = k0 + akk;
            const float* ap = g_h + (size_t)(m0 + arow) * DD + gk;
            float4 v;
            if (gk + 3 < DD) v = *(const float4*)ap;
            else {
                v.x = (gk + 0 < DD) ? ap[0] : 0.f;
                v.y = (gk + 1 < DD) ? ap[1] : 0.f;
                v.z = (gk + 2 < DD) ? ap[2] : 0.f;
                v.w = (gk + 3 < DD) ? ap[3] : 0.f;
            }
            As[akk + 0][arow] = v.x; As[akk + 1][arow] = v.y;
            As[akk + 2][arow] = v.z; As[akk + 3][arow] = v.w;
        }
        { // B tile
            int gk = k0 + bkk;
            int gc = n0 + bcol;
            float4 v = make_float4(0.f, 0.f, 0.f, 0.f);
            if (gk < DD) {
                const float* bp = Wg + (size_t)gk * DD + gc;
                if (gc + 3 < DD) v = *(const float4*)bp;
                else {
                    if (gc + 0 < DD) v.x = bp[0];
                    if (gc + 1 < DD) v.y = bp[1];
                    if (gc + 2 < DD) v.z = bp[2];
                }
            }
            Bs[bkk][bcol + 0] = v.x; Bs[bkk][bcol + 1] = v.y;
            Bs[bkk][bcol + 2] = v.z; Bs[bkk][bcol + 3] = v.w;
        }
        __syncthreads();
#pragma unroll
        for (int kk = 0; kk < TK; kk++) {
            float ra[8], rb[8];
#pragma unroll
            for (int i = 0; i < 8; i++) ra[i] = As[kk][ty * 8 + i];
#pragma unroll
            for (int j = 0; j < 8; j++) rb[j] = Bs[kk][tx * 8 + j];
#pragma unroll
            for (int i = 0; i < 8; i++)
#pragma unroll
                for (int j = 0; j < 8; j++)
                    acc[i][j] = fmaf(ra[i], rb[j], acc[i][j]);
        }
        __syncthreads();
    }
#pragma unroll
    for (int i = 0; i < 8; i++) {
        int m = m0 + ty * 8 + i;
        int b = m / SS, s = m % SS;
        float* outr = g_pre + (size_t)(s * BB + b) * NCOL + g * DD;
#pragma unroll
        for (int j = 0; j < 8; j++) {
            int e = n0 + tx * 8 + j;
            if (e < DD) outr[e] = acc[i][j] + bgp[e];
        }
    }
}

// ---------------- fused recurrent step ----------------
// gates(b, g, e) = pre[s] + h_prev @ R[g]; then sLSTM pointwise update + residual.
// Tile: 32 b x 32 e x 4 gates (= 32x128 GEMM), 128 threads, micro 4b x (2e*4g).
// grid (18, 8)
__global__ void __launch_bounds__(128) k_step(const float* __restrict__ R, int s, int par) {
    const int SB = 32, SE = 32, SK = 16;
    int e0 = blockIdx.x * SE;
    int b0 = blockIdx.y * SB;
    const float* hp = g_hsbuf[par];
    float* hn = g_hsbuf[par ^ 1];
    __shared__ float Hs[SK][SB];
    __shared__ float Rs[SK][SE * 4];   // col = e_local*4 + gate
    int t  = threadIdx.x;  // 128
    int ty = t >> 4;       // 0..7  -> b rows ty*4..+3
    int tx = t & 15;       // 0..15 -> cols tx*8..+7 (= 2 e's x 4 gates)
    float acc[4][8];
#pragma unroll
    for (int i = 0; i < 4; i++)
#pragma unroll
        for (int j = 0; j < 8; j++) acc[i][j] = 0.f;

    int hbrow = t >> 2;        // 0..31
    int hkk0  = (t & 3) * 4;   // 0,4,8,12
    int rkk   = t >> 3;        // 0..15
    int rel0  = (t & 7) * 4;   // 0..28

    for (int k0 = 0; k0 < DD; k0 += SK) {
        { // H tile
            int gk = k0 + hkk0;
            const float* ap = hp + (size_t)(b0 + hbrow) * DD + gk;
            float4 v;
            if (gk + 3 < DD) v = *(const float4*)ap;
            else {
                v.x = (gk + 0 < DD) ? ap[0] : 0.f;
                v.y = (gk + 1 < DD) ? ap[1] : 0.f;
                v.z = (gk + 2 < DD) ? ap[2] : 0.f;
                v.w = (gk + 3 < DD) ? ap[3] : 0.f;
            }
            Hs[hkk0 + 0][hbrow] = v.x; Hs[hkk0 + 1][hbrow] = v.y;
            Hs[hkk0 + 2][hbrow] = v.z; Hs[hkk0 + 3][hbrow] = v.w;
        }
        { // R tile: 4 gates, 4 e's each (float4)
            int gk = k0 + rkk;
            int ge = e0 + rel0;
#pragma unroll
            for (int g = 0; g < 4; g++) {
                float4 v = make_float4(0.f, 0.f, 0.f, 0.f);
                if (gk < DD) {
                    const float* rp = R + (size_t)g * DD * DD + (size_t)gk * DD + ge;
                    if (ge + 3 < DD) v = *(const float4*)rp;
                    else {
                        if (ge + 0 < DD) v.x = rp[0];
                        if (ge + 1 < DD) v.y = rp[1];
                        if (ge + 2 < DD) v.z = rp[2];
                    }
                }
                Rs[rkk][(rel0 + 0) * 4 + g] = v.x;
                Rs[rkk][(rel0 + 1) * 4 + g] = v.y;
                Rs[rkk][(rel0 + 2) * 4 + g] = v.z;
                Rs[rkk][(rel0 + 3) * 4 + g] = v.w;
            }
        }
        __syncthreads();
#pragma unroll
        for (int kk = 0; kk < SK; kk++) {
            float ra[4], rb[8];
#pragma unroll
            for (int i = 0; i < 4; i++) ra[i] = Hs[kk][ty * 4 + i];
#pragma unroll
            for (int j = 0; j < 8; j++) rb[j] = Rs[kk][tx * 8 + j];
#pragma unroll
            for (int i = 0; i < 4; i++)
#pragma unroll
                for (int j = 0; j < 8; j++)
                    acc[i][j] = fmaf(ra[i], rb[j], acc[i][j]);
        }
        __syncthreads();
    }

    // fused sLSTM pointwise update + residual write
#pragma unroll
    for (int ib = 0; ib < 4; ib++) {
        int b = b0 + ty * 4 + ib;
#pragma unroll
        for (int ie = 0; ie < 2; ie++) {
            int e = e0 + tx * 2 + ie;
            if (e >= DD) continue;
            int idx = b * DD + e;
            const float* pr = g_pre + (size_t)(s * BB + b) * NCOL + e;
            float it = acc[ib][ie * 4 + 0] + pr[0 * DD];
            float ft = acc[ib][ie * 4 + 1] + pr[1 * DD];
            float zt = acc[ib][ie * 4 + 2] + pr[2 * DD];
            float ot = acc[ib][ie * 4 + 3] + pr[3 * DD];
            float mo = g_m[idx];
            float mn = fmaxf(ft + mo, it);
            float iv = expf(it - mn);
            float fv = expf(ft + mo - mn);
            float cn = fv * g_c[idx] + iv * tanhf(zt);
            float nn = fv * g_nrm[idx] + iv;
            float sg = 1.f / (1.f + expf(-ot));
            float hv = sg * cn / fmaxf(nn, 1e-6f);
            g_c[idx] = cn; g_nrm[idx] = nn; g_m[idx] = mn;
            hn[idx] = hv;
            g_x[(size_t)(b * SS + s) * DD + e] += hv;
        }
    }
}

// ---------------- batchnorm statistics: per-d over (b,s) ----------------
__global__ void k_bnstats() {
    int d = blockIdx.x;
    __shared__ float r1[256], r2[256];
    float s1 = 0.f, s2 = 0.f;
    for (int r = threadIdx.x; r < ROWS; r += 256) {
        float v = g_x[(size_t)r * DD + d];
        s1 += v; s2 += v * v;
    }
    r1[threadIdx.x] = s1; r2[threadIdx.x] = s2; __syncthreads();
    for (int o = 128; o > 0; o >>= 1) {
        if (threadIdx.x < o) { r1[threadIdx.x] += r1[threadIdx.x + o]; r2[threadIdx.x] += r2[threadIdx.x + o]; }
        __syncthreads();
    }
    if (threadIdx.x == 0) {
        float mu = r1[0] / (float)ROWS;
        float var = r2[0] / (float)ROWS - mu * mu;
        g_mean[d] = mu;
        g_rstd[d] = rsqrtf(var + 1e-5f);
    }
}

// ---------------- final: bn-normalize, reshape (B,P,1128), @ w6, tanh ----------------
__global__ void k_final(const float* __restrict__ w6, const float* __restrict__ b6,
                        const float* __restrict__ bng, const float* __restrict__ bnb,
                        float* __restrict__ out) {
    int bp = blockIdx.x;           // b*PP + p
    int b = bp / PP, p = bp % PP;
    __shared__ float r0[128], r1[128];
    float a0 = 0.f, a1 = 0.f;
    for (int i = threadIdx.x; i < OUTIN; i += 128) {
        int flat = p * OUTIN + i;
        int d = flat / SS, s = flat % SS;
        float v = g_x[(size_t)(b * SS + s) * DD + d];
        float xn = (v - g_mean[d]) * g_rstd[d] * bng[d] + bnb[d];
        a0 += xn * w6[i * 2 + 0];
        a1 += xn * w6[i * 2 + 1];
    }
    r0[threadIdx.x] = a0; r1[threadIdx.x] = a1; __syncthreads();
    for (int o = 64; o > 0; o >>= 1) {
        if (threadIdx.x < o) { r0[threadIdx.x] += r0[threadIdx.x + o]; r1[threadIdx.x] += r1[threadIdx.x + o]; }
        __syncthreads();
    }
    if (threadIdx.x == 0) {
        out[bp * 2 + 0] = tanhf(r0[0] + b6[0]);
        out[bp * 2 + 1] = tanhf(r1[0] + b6[1]);
    }
}

// ---------------- launch ----------------
extern "C" void kernel_launch(void* const* d_in, const int* in_sizes, int n_in,
                              void* d_out, int out_size) {
    const float* inp = (const float*)d_in[0];
    const float* Wg  = (const float*)d_in[1];
    const float* Rg  = (const float*)d_in[2];
    const float* bgp = (const float*)d_in[3];
    const float* lng = (const float*)d_in[4];
    const float* lnb = (const float*)d_in[5];
    const float* bng = (const float*)d_in[6];
    const float* bnb = (const float*)d_in[7];
    const float* w6  = (const float*)d_in[8];
    const float* b6  = (const float*)d_in[9];
    float* out = (float*)d_out;

    k_reshape<<<(ROWS * DD + 255) / 256, 256>>>(inp);
    for (int l = 0; l < NBL; l++) {
        k_zero_state<<<(BB * DD + 255) / 256, 256>>>();
        k_layernorm<<<ROWS, 128>>>(lng + l * DD, lnb + l * DD);
        k_wgemm<<<dim3(5, 80, 4), 256>>>(Wg + (size_t)l * 4 * DD * DD, bgp + (size_t)l * 4 * DD);
        for (int s = 0; s < SS; s++) {
            k_step<<<dim3(18, 8), 128>>>(Rg + (size_t)l * 4 * DD * DD, s, s & 1);
        }
    }
    k_bnstats<<<DD, 256>>>();
    k_final<<<BB * PP, 128>>>(w6, b6, bng, bnb, out);
}

// round 5
// speedup vs baseline: 1.5274x; 1.5274x over previous
#include <cuda_runtime.h>

#define BB 256
#define DD 564
#define SS 40
#define PP 20
#define NBL 6
#define NCOL 2256      /* 4*DD */
#define ROWS 10240     /* BB*SS */
#define OUTIN 1128
#define KPAD 576       /* 18 * 32 */

// ---------------- scratch (static device globals; no allocation) ----------------
__device__ float g_x[ROWS * DD];          // activations (b,s,d)
__device__ float g_h[ROWS * DD];          // layernorm output
__device__ float g_pre[SS * BB * NCOL];   // (s,b,g*D+e)
__device__ float g_c[BB * DD];
__device__ float g_nrm[BB * DD];
__device__ float g_m[BB * DD];
__device__ float g_hsbuf[2][BB * DD];     // double-buffered hidden state
__device__ float g_mean[DD];
__device__ float g_rstd[DD];

// ---------------- tf32 helpers ----------------
__device__ __forceinline__ unsigned f2tf(float f) {
    unsigned r;
    asm("cvt.rna.tf32.f32 %0, %1;" : "=r"(r) : "f"(f));
    return r;
}

// split f into tf32 hi + tf32 lo (3xTF32 trick -> ~fp32 accuracy)
__device__ __forceinline__ void store4split(unsigned* ph, unsigned* pl, float4 v) {
    float f[4] = {v.x, v.y, v.z, v.w};
#pragma unroll
    for (int i = 0; i < 4; i++) {
        unsigned h = f2tf(f[i]);
        ph[i] = h;
        pl[i] = f2tf(f[i] - __uint_as_float(h));
    }
}

__device__ __forceinline__ void mma8(float* d, const unsigned* a, const unsigned* b) {
    asm volatile(
        "mma.sync.aligned.m16n8k8.row.col.f32.tf32.tf32.f32 "
        "{%0,%1,%2,%3}, {%4,%5,%6,%7}, {%8,%9}, {%0,%1,%2,%3};"
        : "+f"(d[0]), "+f"(d[1]), "+f"(d[2]), "+f"(d[3])
        : "r"(a[0]), "r"(a[1]), "r"(a[2]), "r"(a[3]), "r"(b[0]), "r"(b[1]));
}

// ---------------- input reshape: inp(b, d*S+s) -> x(b,s,d) ----------------
__global__ void k_reshape(const float* __restrict__ inp) {
    int idx = blockIdx.x * blockDim.x + threadIdx.x;
    if (idx >= ROWS * DD) return;
    int d = idx % DD;
    int r = idx / DD;
    int s = r % SS;
    int b = r / SS;
    g_x[idx] = inp[(size_t)b * (DD * SS) + d * SS + s];
}

__global__ void k_zero_state() {
    int idx = blockIdx.x * blockDim.x + threadIdx.x;
    if (idx < BB * DD) {
        g_c[idx] = 0.f; g_nrm[idx] = 0.f; g_m[idx] = 0.f;
        g_hsbuf[0][idx] = 0.f; g_hsbuf[1][idx] = 0.f;
    }
}

// ---------------- per-row layernorm over D ----------------
__global__ void k_layernorm(const float* __restrict__ lng, const float* __restrict__ lnb) {
    int row = blockIdx.x;
    const float* xr = g_x + (size_t)row * DD;
    __shared__ float red[128];
    __shared__ float s_mu, s_rs;
    float s1 = 0.f, s2 = 0.f;
    for (int d = threadIdx.x; d < DD; d += 128) { float v = xr[d]; s1 += v; s2 += v * v; }
    red[threadIdx.x] = s1; __syncthreads();
    for (int o = 64; o > 0; o >>= 1) { if (threadIdx.x < o) red[threadIdx.x] += red[threadIdx.x + o]; __syncthreads(); }
    if (threadIdx.x == 0) s_mu = red[0] / DD;
    __syncthreads();
    red[threadIdx.x] = s2; __syncthreads();
    for (int o = 64; o > 0; o >>= 1) { if (threadIdx.x < o) red[threadIdx.x] += red[threadIdx.x + o]; __syncthreads(); }
    if (threadIdx.x == 0) {
        float var = red[0] / DD - s_mu * s_mu;
        s_rs = rsqrtf(var + 1e-5f);
    }
    __syncthreads();
    float mu = s_mu, rs = s_rs;
    for (int d = threadIdx.x; d < DD; d += 128)
        g_h[(size_t)row * DD + d] = (xr[d] - mu) * rs * lng[d] + lnb[d];
}

// ---------------- W GEMM via tf32 tensor cores ----------------
// pre[s,b,g*D+e] = h(row m=b*S+s,:) @ W[g] + bias[g]
// Block tile 64m x 64n x 32k, 128 threads = 4 warps (2x2), warp tile 32x32.
// 3x tf32 split for ~fp32 accuracy.  grid (9, 160, 4)
__global__ void __launch_bounds__(128) k_wgemm_mma(const float* __restrict__ W,
                                                   const float* __restrict__ bias) {
    int g  = blockIdx.z;
    int n0 = blockIdx.x * 64;
    int m0 = blockIdx.y * 64;
    __shared__ unsigned Ah[64][36], Al[64][36], Bh[32][72], Bl[32][72];
    int t = threadIdx.x, lane = t & 31, wid = t >> 5;
    int wm = wid >> 1, wn = wid & 1;
    const float* Wg = W + (size_t)g * DD * DD;

    float acc[2][4][4];
#pragma unroll
    for (int i = 0; i < 2; i++)
#pragma unroll
        for (int j = 0; j < 4; j++)
#pragma unroll
            for (int k = 0; k < 4; k++) acc[i][j][k] = 0.f;

    for (int k0 = 0; k0 < KPAD; k0 += 32) {
        { // A tile: 64 rows x 32 k
            int r = t >> 1, kb = t & 1;
            const float* ap = g_h + (size_t)(m0 + r) * DD;
#pragma unroll
            for (int j = 0; j < 4; j++) {
                int kk = (kb + 2 * j) * 4;
                int gk = k0 + kk;
                float4 v = make_float4(0.f, 0.f, 0.f, 0.f);
                if (gk + 3 < DD) v = *(const float4*)(ap + gk);
                else if (gk < DD) {
                    v.x = ap[gk];
                    if (gk + 1 < DD) v.y = ap[gk + 1];
                    if (gk + 2 < DD) v.z = ap[gk + 2];
                }
                store4split(&Ah[r][kk], &Al[r][kk], v);
            }
        }
        { // B tile: 32 k x 64 e
            int kq = t >> 2, eq = t & 3;
            int gk = k0 + kq;
            const float* wp = Wg + (size_t)gk * DD;
#pragma unroll
            for (int j = 0; j < 4; j++) {
                int e = (eq + 4 * j) * 4;
                int ge = n0 + e;
                float4 v = make_float4(0.f, 0.f, 0.f, 0.f);
                if (gk < DD) {
                    if (ge + 3 < DD) v = *(const float4*)(wp + ge);
                    else if (ge < DD) {
                        v.x = wp[ge];
                        if (ge + 1 < DD) v.y = wp[ge + 1];
                        if (ge + 2 < DD) v.z = wp[ge + 2];
                    }
                }
                store4split(&Bh[kq][e], &Bl[kq][e], v);
            }
        }
        __syncthreads();
#pragma unroll
        for (int ks = 0; ks < 4; ks++) {
            int kk = ks * 8;
            unsigned ah[2][4], al[2][4], bh[4][2], bl[4][2];
#pragma unroll
            for (int mi = 0; mi < 2; mi++) {
                int row = wm * 32 + mi * 16 + (lane >> 2);
                int c = kk + (lane & 3);
                ah[mi][0] = Ah[row][c];     ah[mi][1] = Ah[row + 8][c];
                ah[mi][2] = Ah[row][c + 4]; ah[mi][3] = Ah[row + 8][c + 4];
                al[mi][0] = Al[row][c];     al[mi][1] = Al[row + 8][c];
                al[mi][2] = Al[row][c + 4]; al[mi][3] = Al[row + 8][c + 4];
            }
#pragma unroll
            for (int ni = 0; ni < 4; ni++) {
                int cb = wn * 32 + ni * 8 + (lane >> 2);
                int rk = kk + (lane & 3);
                bh[ni][0] = Bh[rk][cb]; bh[ni][1] = Bh[rk + 4][cb];
                bl[ni][0] = Bl[rk][cb]; bl[ni][1] = Bl[rk + 4][cb];
            }
#pragma unroll
            for (int mi = 0; mi < 2; mi++)
#pragma unroll
                for (int ni = 0; ni < 4; ni++) {
                    mma8(acc[mi][ni], ah[mi], bh[ni]);
                    mma8(acc[mi][ni], ah[mi], bl[ni]);
                    mma8(acc[mi][ni], al[mi], bh[ni]);
                }
        }
        __syncthreads();
    }
    // epilogue: + bias, scatter to g_pre
    const float* bp = bias + g * DD;
#pragma unroll
    for (int mi = 0; mi < 2; mi++) {
#pragma unroll
        for (int ni = 0; ni < 4; ni++) {
            int col = wn * 32 + ni * 8 + (lane & 3) * 2;
            int e = n0 + col;
            int row0 = m0 + wm * 32 + mi * 16 + (lane >> 2);
            int row1 = row0 + 8;
            int b0r = row0 / SS, s0r = row0 % SS;
            int b1r = row1 / SS, s1r = row1 % SS;
            float* o0 = g_pre + (size_t)(s0r * BB + b0r) * NCOL + g * DD;
            float* o1 = g_pre + (size_t)(s1r * BB + b1r) * NCOL + g * DD;
            if (e < DD)     { o0[e]     = acc[mi][ni][0] + bp[e];     o1[e]     = acc[mi][ni][2] + bp[e]; }
            if (e + 1 < DD) { o0[e + 1] = acc[mi][ni][1] + bp[e + 1]; o1[e + 1] = acc[mi][ni][3] + bp[e + 1]; }
        }
    }
}

// ---------------- fused recurrent step via tf32 tensor cores ----------------
// gates(b, col=e*4+g) = h_prev @ R (gate-interleaved columns), then fused
// sLSTM pointwise update + residual. Block tile 64b x (16e*4g), 4 warps (2x2).
// grid (36, 4)
__global__ void __launch_bounds__(128) k_step_mma(const float* __restrict__ R, int s, int par) {
    int e0 = blockIdx.x * 16;
    int b0 = blockIdx.y * 64;
    __shared__ unsigned Ah[64][36], Al[64][36], Bh[32][72], Bl[32][72];
    int t = threadIdx.x, lane = t & 31, wid = t >> 5;
    int wm = wid >> 1, wn = wid & 1;
    const float* hp = g_hsbuf[par];
    float* hn = g_hsbuf[par ^ 1];

    float acc[2][4][4];
#pragma unroll
    for (int i = 0; i < 2; i++)
#pragma unroll
        for (int j = 0; j < 4; j++)
#pragma unroll
            for (int k = 0; k < 4; k++) acc[i][j][k] = 0.f;

    for (int k0 = 0; k0 < KPAD; k0 += 32) {
        { // A tile: h_prev 64 rows x 32 k
            int r = t >> 1, kb = t & 1;
            const float* ap = hp + (size_t)(b0 + r) * DD;
#pragma unroll
            for (int j = 0; j < 4; j++) {
                int kk = (kb + 2 * j) * 4;
                int gk = k0 + kk;
                float4 v = make_float4(0.f, 0.f, 0.f, 0.f);
                if (gk + 3 < DD) v = *(const float4*)(ap + gk);
                else if (gk < DD) {
                    v.x = ap[gk];
                    if (gk + 1 < DD) v.y = ap[gk + 1];
                    if (gk + 2 < DD) v.z = ap[gk + 2];
                }
                store4split(&Ah[r][kk], &Al[r][kk], v);
            }
        }
        { // B tile: R, gate-interleaved cols: Bs[k][e_local*4+g]
            int gq = t & 3, kq = t >> 2;
            int gk = k0 + kq;
            const float* rp = R + (size_t)gq * DD * DD + (size_t)gk * DD;
#pragma unroll
            for (int eg = 0; eg < 4; eg++) {
                int e = eg * 4;
                int ge = e0 + e;
                float4 v = make_float4(0.f, 0.f, 0.f, 0.f);
                if (gk < DD) {
                    if (ge + 3 < DD) v = *(const float4*)(rp + ge);
                    else if (ge < DD) {
                        v.x = rp[ge];
                        if (ge + 1 < DD) v.y = rp[ge + 1];
                        if (ge + 2 < DD) v.z = rp[ge + 2];
                    }
                }
                float f[4] = {v.x, v.y, v.z, v.w};
#pragma unroll
                for (int i = 0; i < 4; i++) {
                    unsigned h = f2tf(f[i]);
                    Bh[kq][(e + i) * 4 + gq] = h;
                    Bl[kq][(e + i) * 4 + gq] = f2tf(f[i] - __uint_as_float(h));
                }
            }
        }
        __syncthreads();
#pragma unroll
        for (int ks = 0; ks < 4; ks++) {
            int kk = ks * 8;
            unsigned ah[2][4], al[2][4], bh[4][2], bl[4][2];
#pragma unroll
            for (int mi = 0; mi < 2; mi++) {
                int row = wm * 32 + mi * 16 + (lane >> 2);
                int c = kk + (lane & 3);
                ah[mi][0] = Ah[row][c];     ah[mi][1] = Ah[row + 8][c];
                ah[mi][2] = Ah[row][c + 4]; ah[mi][3] = Ah[row + 8][c + 4];
                al[mi][0] = Al[row][c];     al[mi][1] = Al[row + 8][c];
                al[mi][2] = Al[row][c + 4]; al[mi][3] = Al[row + 8][c + 4];
            }
#pragma unroll
            for (int ni = 0; ni < 4; ni++) {
                int cb = wn * 32 + ni * 8 + (lane >> 2);
                int rk = kk + (lane & 3);
                bh[ni][0] = Bh[rk][cb]; bh[ni][1] = Bh[rk + 4][cb];
                bl[ni][0] = Bl[rk][cb]; bl[ni][1] = Bl[rk + 4][cb];
            }
#pragma unroll
            for (int mi = 0; mi < 2; mi++)
#pragma unroll
                for (int ni = 0; ni < 4; ni++) {
                    mma8(acc[mi][ni], ah[mi], bh[ni]);
                    mma8(acc[mi][ni], ah[mi], bl[ni]);
                    mma8(acc[mi][ni], al[mi], bh[ni]);
                }
        }
        __syncthreads();
    }

    // fused sLSTM epilogue.
    // Thread cols c,c+1: for lane%4 in {0,2}: gates (i,f); partner lane^1 has (z,o)
    // of the SAME (b,e). Exchange via shfl_xor(1); even lanes do the update.
#pragma unroll
    for (int mi = 0; mi < 2; mi++) {
#pragma unroll
        for (int ni = 0; ni < 4; ni++) {
            float d0 = acc[mi][ni][0], d1 = acc[mi][ni][1];
            float d2 = acc[mi][ni][2], d3 = acc[mi][ni][3];
            float p0 = __shfl_xor_sync(0xffffffffu, d0, 1);
            float p1 = __shfl_xor_sync(0xffffffffu, d1, 1);
            float p2 = __shfl_xor_sync(0xffffffffu, d2, 1);
            float p3 = __shfl_xor_sync(0xffffffffu, d3, 1);
            if ((lane & 1) == 0) {
                int e = e0 + wn * 8 + ni * 2 + ((lane & 3) >> 1);
                if (e < DD) {
                    int b = b0 + wm * 32 + mi * 16 + (lane >> 2);
#pragma unroll
                    for (int rr = 0; rr < 2; rr++) {
                        int bb = b + rr * 8;
                        float itg = rr ? d2 : d0;
                        float ftg = rr ? d3 : d1;
                        float ztg = rr ? p2 : p0;
                        float otg = rr ? p3 : p1;
                        int idx = bb * DD + e;
                        const float* pr = g_pre + (size_t)(s * BB + bb) * NCOL + e;
                        float it = itg + pr[0 * DD];
                        float ft = ftg + pr[1 * DD];
                        float zt = ztg + pr[2 * DD];
                        float ot = otg + pr[3 * DD];
                        float mo = g_m[idx];
                        float mn = fmaxf(ft + mo, it);
                        float iv = expf(it - mn);
                        float fv = expf(ft + mo - mn);
                        float cn = fv * g_c[idx] + iv * tanhf(zt);
                        float nn = fv * g_nrm[idx] + iv;
                        float sg = 1.f / (1.f + expf(-ot));
                        float hv = sg * cn / fmaxf(nn, 1e-6f);
                        g_c[idx] = cn; g_nrm[idx] = nn; g_m[idx] = mn;
                        hn[idx] = hv;
                        g_x[(size_t)(bb * SS + s) * DD + e] += hv;
                    }
                }
            }
        }
    }
}

// ---------------- batchnorm statistics: per-d over (b,s) ----------------
__global__ void k_bnstats() {
    int d = blockIdx.x;
    __shared__ float r1[256], r2[256];
    float s1 = 0.f, s2 = 0.f;
    for (int r = threadIdx.x; r < ROWS; r += 256) {
        float v = g_x[(size_t)r * DD + d];
        s1 += v; s2 += v * v;
    }
    r1[threadIdx.x] = s1; r2[threadIdx.x] = s2; __syncthreads();
    for (int o = 128; o > 0; o >>= 1) {
        if (threadIdx.x < o) { r1[threadIdx.x] += r1[threadIdx.x + o]; r2[threadIdx.x] += r2[threadIdx.x + o]; }
        __syncthreads();
    }
    if (threadIdx.x == 0) {
        float mu = r1[0] / (float)ROWS;
        float var = r2[0] / (float)ROWS - mu * mu;
        g_mean[d] = mu;
        g_rstd[d] = rsqrtf(var + 1e-5f);
    }
}

// ---------------- final: bn-normalize, reshape (B,P,1128), @ w6, tanh ----------------
__global__ void k_final(const float* __restrict__ w6, const float* __restrict__ b6,
                        const float* __restrict__ bng, const float* __restrict__ bnb,
                        float* __restrict__ out) {
    int bp = blockIdx.x;           // b*PP + p
    int b = bp / PP, p = bp % PP;
    __shared__ float r0[128], r1[128];
    float a0 = 0.f, a1 = 0.f;
    for (int i = threadIdx.x; i < OUTIN; i += 128) {
        int flat = p * OUTIN + i;
        int d = flat / SS, s = flat % SS;
        float v = g_x[(size_t)(b * SS + s) * DD + d];
        float xn = (v - g_mean[d]) * g_rstd[d] * bng[d] + bnb[d];
        a0 += xn * w6[i * 2 + 0];
        a1 += xn * w6[i * 2 + 1];
    }
    r0[threadIdx.x] = a0; r1[threadIdx.x] = a1; __syncthreads();
    for (int o = 64; o > 0; o >>= 1) {
        if (threadIdx.x < o) { r0[threadIdx.x] += r0[threadIdx.x + o]; r1[threadIdx.x] += r1[threadIdx.x + o]; }
        __syncthreads();
    }
    if (threadIdx.x == 0) {
        out[bp * 2 + 0] = tanhf(r0[0] + b6[0]);
        out[bp * 2 + 1] = tanhf(r1[0] + b6[1]);
    }
}

// ---------------- launch ----------------
extern "C" void kernel_launch(void* const* d_in, const int* in_sizes, int n_in,
                              void* d_out, int out_size) {
    const float* inp = (const float*)d_in[0];
    const float* Wg  = (const float*)d_in[1];
    const float* Rg  = (const float*)d_in[2];
    const float* bgp = (const float*)d_in[3];
    const float* lng = (const float*)d_in[4];
    const float* lnb = (const float*)d_in[5];
    const float* bng = (const float*)d_in[6];
    const float* bnb = (const float*)d_in[7];
    const float* w6  = (const float*)d_in[8];
    const float* b6  = (const float*)d_in[9];
    float* out = (float*)d_out;

    k_reshape<<<(ROWS * DD + 255) / 256, 256>>>(inp);
    for (int l = 0; l < NBL; l++) {
        k_zero_state<<<(BB * DD + 255) / 256, 256>>>();
        k_layernorm<<<ROWS, 128>>>(lng + l * DD, lnb + l * DD);
        k_wgemm_mma<<<dim3(9, 160, 4), 128>>>(Wg + (size_t)l * 4 * DD * DD,
                                              bgp + (size_t)l * 4 * DD);
        for (int s = 0; s < SS; s++) {
            k_step_mma<<<dim3(36, 4), 128>>>(Rg + (size_t)l * 4 * DD * DD, s, s & 1);
        }
    }
    k_bnstats<<<DD, 256>>>();
    k_final<<<BB * PP, 128>>>(w6, b6, bng, bnb, out);
}

// round 8
// speedup vs baseline: 1.6256x; 1.0643x over previous
#include <cuda_runtime.h>

#define BB 256
#define DD 564
#define SS 40
#define PP 20
#define NBL 6
#define NCOL 2256      /* 4*DD */
#define ROWS 10240     /* BB*SS */
#define OUTIN 1128
#define KPAD 576       /* 18 * 32 */

// ---------------- scratch (static device globals; no allocation) ----------------
__device__ float g_x[ROWS * DD];           // activations (b,s,d)
__device__ float g_pre[SS * BB * NCOL];    // (s,b, e*4+g)  gate-interleaved
__device__ float g_c[BB * DD];
__device__ float g_nrm[BB * DD];
__device__ float g_m[BB * DD];
__device__ float g_mean[DD];
__device__ float g_rstd[DD];
__device__ uint2 g_hsp[ROWS * DD];         // layernorm out, split tf32 {hi,lo}
__device__ uint2 g_Wsp[4 * DD * DD];       // W split, layout [g][d][e]
__device__ uint2 g_Rsp[DD * NCOL];         // R split, layout [d][e*4+g]
__device__ uint2 g_hssp[2][BB * DD];       // hidden state split, double buffered

// ---------------- tf32 helpers ----------------
__device__ __forceinline__ unsigned f2tf(float f) {
    unsigned r;
    asm("cvt.rna.tf32.f32 %0, %1;" : "=r"(r) : "f"(f));
    return r;
}
__device__ __forceinline__ uint2 split2(float f) {
    unsigned h = f2tf(f);
    return make_uint2(h, f2tf(f - __uint_as_float(h)));
}
__device__ __forceinline__ void mma8(float* d, const unsigned* a, const unsigned* b) {
    asm volatile(
        "mma.sync.aligned.m16n8k8.row.col.f32.tf32.tf32.f32 "
        "{%0,%1,%2,%3}, {%4,%5,%6,%7}, {%8,%9}, {%0,%1,%2,%3};"
        : "+f"(d[0]), "+f"(d[1]), "+f"(d[2]), "+f"(d[3])
        : "r"(a[0]), "r"(a[1]), "r"(a[2]), "r"(a[3]), "r"(b[0]), "r"(b[1]));
}

// ---------------- input reshape: inp(b, d*S+s) -> x(b,s,d) ----------------
__global__ void k_reshape(const float* __restrict__ inp) {
    int idx = blockIdx.x * blockDim.x + threadIdx.x;
    if (idx >= ROWS * DD) return;
    int d = idx % DD;
    int r = idx / DD;
    int s = r % SS;
    int b = r / SS;
    g_x[idx] = inp[(size_t)b * (DD * SS) + d * SS + s];
}

__global__ void k_zero_state() {
    int idx = blockIdx.x * blockDim.x + threadIdx.x;
    if (idx < BB * DD) {
        g_c[idx] = 0.f; g_nrm[idx] = 0.f; g_m[idx] = 0.f;
        g_hssp[0][idx] = make_uint2(0u, 0u);
        g_hssp[1][idx] = make_uint2(0u, 0u);
    }
}

// ---------------- per-layer weight pre-split ----------------
__global__ void k_convW(const float* __restrict__ W) {
    int i = blockIdx.x * blockDim.x + threadIdx.x;
    if (i >= 4 * DD * DD) return;
    g_Wsp[i] = split2(W[i]);
}
__global__ void k_convR(const float* __restrict__ R) {
    int i = blockIdx.x * blockDim.x + threadIdx.x;
    if (i >= 4 * DD * DD) return;
    int g = i / (DD * DD);
    int rem = i - g * DD * DD;
    int d = rem / DD;
    int e = rem - d * DD;
    g_Rsp[d * NCOL + e * 4 + g] = split2(R[i]);
}

// ---------------- per-row layernorm over D, emits split tf32 ----------------
__global__ void k_layernorm(const float* __restrict__ lng, const float* __restrict__ lnb) {
    int row = blockIdx.x;
    const float* xr = g_x + (size_t)row * DD;
    __shared__ float red[128];
    __shared__ float s_mu, s_rs;
    float s1 = 0.f, s2 = 0.f;
    for (int d = threadIdx.x; d < DD; d += 128) { float v = xr[d]; s1 += v; s2 += v * v; }
    red[threadIdx.x] = s1; __syncthreads();
    for (int o = 64; o > 0; o >>= 1) { if (threadIdx.x < o) red[threadIdx.x] += red[threadIdx.x + o]; __syncthreads(); }
    if (threadIdx.x == 0) s_mu = red[0] / DD;
    __syncthreads();
    red[threadIdx.x] = s2; __syncthreads();
    for (int o = 64; o > 0; o >>= 1) { if (threadIdx.x < o) red[threadIdx.x] += red[threadIdx.x + o]; __syncthreads(); }
    if (threadIdx.x == 0) {
        float var = red[0] / DD - s_mu * s_mu;
        s_rs = rsqrtf(var + 1e-5f);
    }
    __syncthreads();
    float mu = s_mu, rs = s_rs;
    for (int d = threadIdx.x; d < DD; d += 128) {
        float h = (xr[d] - mu) * rs * lng[d] + lnb[d];
        g_hsp[(size_t)row * DD + d] = split2(h);
    }
}

// ===================== shared GEMM tiling =====================
// Block 64m x 64n x 32k, 128 threads, 4 warps (2x2), warp tile 32x32.
// Smem strides 36/68 uint2 (==4 mod 16) -> 2-way max on 8B frag loads.

// ---------------- W GEMM: pre = h @ W + bias (per gate) -> interleaved g_pre ----
__global__ void __launch_bounds__(128) k_wgemm(const float* __restrict__ bias) {
    __shared__ uint2 As2[64][36];
    __shared__ uint2 Bs2[32][68];
    int g  = blockIdx.z;
    int n0 = blockIdx.x * 64;
    int m0 = blockIdx.y * 64;
    int t = threadIdx.x, lane = t & 31, wid = t >> 5;
    int wm = wid >> 1, wn = wid & 1;

    float acc[2][4][4];
#pragma unroll
    for (int i = 0; i < 2; i++)
#pragma unroll
        for (int j = 0; j < 4; j++)
#pragma unroll
            for (int k = 0; k < 4; k++) acc[i][j][k] = 0.f;

    int ar = t >> 1, akb = (t & 1) * 16;              // A: row, k-base
    int bkq = t >> 2, bcq = (t & 3) * 16;             // B: k-row, col-base
    const uint2* Asrc = g_hsp + (size_t)(m0 + ar) * DD;
    const uint2* Bsrc = g_Wsp + (size_t)g * DD * DD;

    for (int k0 = 0; k0 < KPAD; k0 += 32) {
#pragma unroll
        for (int j = 0; j < 8; j++) {                 // A tile 64x32
            int kk = akb + j * 2;
            int gk = k0 + kk;
            uint4 v = make_uint4(0u, 0u, 0u, 0u);
            if (gk < DD) v = *(const uint4*)(Asrc + gk);
            *(uint4*)&As2[ar][kk] = v;
        }
        {
            int gk = k0 + bkq;
            const uint2* wp = Bsrc + (size_t)gk * DD + n0;
#pragma unroll
            for (int j = 0; j < 8; j++) {             // B tile 32x64
                int c = bcq + j * 2;
                int ge = n0 + c;
                uint4 v = make_uint4(0u, 0u, 0u, 0u);
                if (gk < DD && ge < DD) v = *(const uint4*)(wp + c);
                *(uint4*)&Bs2[bkq][c] = v;
            }
        }
        __syncthreads();
#pragma unroll
        for (int ks = 0; ks < 4; ks++) {
            int kk = ks * 8;
            int c = kk + (lane & 3);
            int rk = c;
            unsigned ah[2][4], al[2][4], bh[4][2], bl[4][2];
#pragma unroll
            for (int mi = 0; mi < 2; mi++) {
                int row = wm * 32 + mi * 16 + (lane >> 2);
                uint2 a00 = As2[row][c],     a01 = As2[row + 8][c];
                uint2 a10 = As2[row][c + 4], a11 = As2[row + 8][c + 4];
                ah[mi][0] = a00.x; ah[mi][1] = a01.x; ah[mi][2] = a10.x; ah[mi][3] = a11.x;
                al[mi][0] = a00.y; al[mi][1] = a01.y; al[mi][2] = a10.y; al[mi][3] = a11.y;
            }
#pragma unroll
            for (int ni = 0; ni < 4; ni++) {
                int cb = wn * 32 + ni * 8 + (lane >> 2);
                uint2 b0 = Bs2[rk][cb], b1 = Bs2[rk + 4][cb];
                bh[ni][0] = b0.x; bh[ni][1] = b1.x;
                bl[ni][0] = b0.y; bl[ni][1] = b1.y;
            }
#pragma unroll
            for (int mi = 0; mi < 2; mi++)
#pragma unroll
                for (int ni = 0; ni < 4; ni++) {
                    mma8(acc[mi][ni], ah[mi], bh[ni]);
                    mma8(acc[mi][ni], ah[mi], bl[ni]);
                    mma8(acc[mi][ni], al[mi], bh[ni]);
                }
        }
        __syncthreads();
    }
    // epilogue: + bias, scatter to interleaved g_pre
    const float* bp = bias + g * DD;
#pragma unroll
    for (int mi = 0; mi < 2; mi++) {
        int row0 = m0 + wm * 32 + mi * 16 + (lane >> 2);
        int row1 = row0 + 8;
        int b0r = row0 / SS, s0r = row0 - b0r * SS;
        int b1r = row1 / SS, s1r = row1 - b1r * SS;
        float* o0 = g_pre + (size_t)(s0r * BB + b0r) * NCOL + g;
        float* o1 = g_pre + (size_t)(s1r * BB + b1r) * NCOL + g;
#pragma unroll
        for (int ni = 0; ni < 4; ni++) {
            int e = n0 + wn * 32 + ni * 8 + (lane & 3) * 2;
            if (e < DD) {
                float bv0 = bp[e], bv1 = bp[e + 1];
                o0[(e) * 4]     = acc[mi][ni][0] + bv0;
                o0[(e + 1) * 4] = acc[mi][ni][1] + bv1;
                o1[(e) * 4]     = acc[mi][ni][2] + bv0;
                o1[(e + 1) * 4] = acc[mi][ni][3] + bv1;
            }
        }
    }
}

// ---------------- fused recurrent step ----------------
// gates(b, e*4+g) = h_prev @ Rsp; fused sLSTM pointwise update + residual.
// grid (36, 4): cols 36*64=2304 >= 2256, b 4*64=256.
__global__ void __launch_bounds__(128) k_step(int s, int par) {
    __shared__ uint2 As2[64][36];
    __shared__ uint2 Bs2[32][68];
    int c0 = blockIdx.x * 64;
    int b0 = blockIdx.y * 64;
    int t = threadIdx.x, lane = t & 31, wid = t >> 5;
    int wm = wid >> 1, wn = wid & 1;
    const uint2* hp = g_hssp[par];
    uint2* hn = g_hssp[par ^ 1];

    float acc[2][4][4];
#pragma unroll
    for (int i = 0; i < 2; i++)
#pragma unroll
        for (int j = 0; j < 4; j++)
#pragma unroll
            for (int k = 0; k < 4; k++) acc[i][j][k] = 0.f;

    int ar = t >> 1, akb = (t & 1) * 16;
    int bkq = t >> 2, bcq = (t & 3) * 16;
    const uint2* Asrc = hp + (size_t)(b0 + ar) * DD;

    for (int k0 = 0; k0 < KPAD; k0 += 32) {
#pragma unroll
        for (int j = 0; j < 8; j++) {                 // A tile 64x32 (h_prev)
            int kk = akb + j * 2;
            int gk = k0 + kk;
            uint4 v = make_uint4(0u, 0u, 0u, 0u);
            if (gk < DD) v = *(const uint4*)(Asrc + gk);
            *(uint4*)&As2[ar][kk] = v;
        }
        {
            int gk = k0 + bkq;
            const uint2* rp = g_Rsp + (size_t)gk * NCOL + c0;
#pragma unroll
            for (int j = 0; j < 8; j++) {             // B tile 32x64 (R interleaved)
                int c = bcq + j * 2;
                int gc = c0 + c;
                uint4 v = make_uint4(0u, 0u, 0u, 0u);
                if (gk < DD && gc < NCOL) v = *(const uint4*)(rp + c);
                *(uint4*)&Bs2[bkq][c] = v;
            }
        }
        __syncthreads();
#pragma unroll
        for (int ks = 0; ks < 4; ks++) {
            int kk = ks * 8;
            int c = kk + (lane & 3);
            unsigned ah[2][4], al[2][4], bh[4][2], bl[4][2];
#pragma unroll
            for (int mi = 0; mi < 2; mi++) {
                int row = wm * 32 + mi * 16 + (lane >> 2);
                uint2 a00 = As2[row][c],     a01 = As2[row + 8][c];
                uint2 a10 = As2[row][c + 4], a11 = As2[row + 8][c + 4];
                ah[mi][0] = a00.x; ah[mi][1] = a01.x; ah[mi][2] = a10.x; ah[mi][3] = a11.x;
                al[mi][0] = a00.y; al[mi][1] = a01.y; al[mi][2] = a10.y; al[mi][3] = a11.y;
            }
#pragma unroll
            for (int ni = 0; ni < 4; ni++) {
                int cb = wn * 32 + ni * 8 + (lane >> 2);
                uint2 b0 = Bs2[c][cb], b1 = Bs2[c + 4][cb];
                bh[ni][0] = b0.x; bh[ni][1] = b1.x;
                bl[ni][0] = b0.y; bl[ni][1] = b1.y;
            }
#pragma unroll
            for (int mi = 0; mi < 2; mi++)
#pragma unroll
                for (int ni = 0; ni < 4; ni++) {
                    mma8(acc[mi][ni], ah[mi], bh[ni]);
                    mma8(acc[mi][ni], ah[mi], bl[ni]);
                    mma8(acc[mi][ni], al[mi], bh[ni]);
                }
        }
        __syncthreads();
    }

    // fused sLSTM epilogue. Even lane holds gates (i,f) of one e; partner
    // lane^1 holds (z,o) of the SAME e. shfl_xor(1) recombines.
#pragma unroll
    for (int mi = 0; mi < 2; mi++) {
#pragma unroll
        for (int ni = 0; ni < 4; ni++) {
            float d0 = acc[mi][ni][0], d1 = acc[mi][ni][1];
            float d2 = acc[mi][ni][2], d3 = acc[mi][ni][3];
            float p0 = __shfl_xor_sync(0xffffffffu, d0, 1);
            float p1 = __shfl_xor_sync(0xffffffffu, d1, 1);
            float p2 = __shfl_xor_sync(0xffffffffu, d2, 1);
            float p3 = __shfl_xor_sync(0xffffffffu, d3, 1);
            if ((lane & 1) == 0) {
                int c = c0 + wn * 32 + ni * 8 + (lane & 3) * 2;  // col of gate0
                if (c < NCOL) {
                    int e = c >> 2;
                    int b = b0 + wm * 32 + mi * 16 + (lane >> 2);
#pragma unroll
                    for (int rr = 0; rr < 2; rr++) {
                        int bb = b + rr * 8;
                        float itg = rr ? d2 : d0;
                        float ftg = rr ? d3 : d1;
                        float ztg = rr ? p2 : p0;
                        float otg = rr ? p3 : p1;
                        int idx = bb * DD + e;
                        float4 pr = *(const float4*)(g_pre + (size_t)(s * BB + bb) * NCOL + (e << 2));
                        float it = itg + pr.x;
                        float ft = ftg + pr.y;
                        float zt = ztg + pr.z;
                        float ot = otg + pr.w;
                        float mo = g_m[idx];
                        float mn = fmaxf(ft + mo, it);
                        float iv = expf(it - mn);
                        float fv = expf(ft + mo - mn);
                        float cn = fv * g_c[idx] + iv * tanhf(zt);
                        float nn = fv * g_nrm[idx] + iv;
                        float sg = 1.f / (1.f + expf(-ot));
                        float hv = sg * cn / fmaxf(nn, 1e-6f);
                        g_c[idx] = cn; g_nrm[idx] = nn; g_m[idx] = mn;
                        hn[idx] = split2(hv);
                        g_x[(size_t)(bb * SS + s) * DD + e] += hv;
                    }
                }
            }
        }
    }
}

// ---------------- batchnorm statistics: per-d over (b,s) ----------------
__global__ void k_bnstats() {
    int d = blockIdx.x;
    __shared__ float r1[256], r2[256];
    float s1 = 0.f, s2 = 0.f;
    for (int r = threadIdx.x; r < ROWS; r += 256) {
        float v = g_x[(size_t)r * DD + d];
        s1 += v; s2 += v * v;
    }
    r1[threadIdx.x] = s1; r2[threadIdx.x] = s2; __syncthreads();
    for (int o = 128; o > 0; o >>= 1) {
        if (threadIdx.x < o) { r1[threadIdx.x] += r1[threadIdx.x + o]; r2[threadIdx.x] += r2[threadIdx.x + o]; }
        __syncthreads();
    }
    if (threadIdx.x == 0) {
        float mu = r1[0] / (float)ROWS;
        float var = r2[0] / (float)ROWS - mu * mu;
        g_mean[d] = mu;
        g_rstd[d] = rsqrtf(var + 1e-5f);
    }
}

// ---------------- final: bn-normalize, reshape (B,P,1128), @ w6, tanh ----------------
__global__ void k_final(const float* __restrict__ w6, const float* __restrict__ b6,
                        const float* __restrict__ bng, const float* __restrict__ bnb,
                        float* __restrict__ out) {
    int bp = blockIdx.x;           // b*PP + p
    int b = bp / PP, p = bp % PP;
    __shared__ float r0[128], r1[128];
    float a0 = 0.f, a1 = 0.f;
    for (int i = threadIdx.x; i < OUTIN; i += 128) {
        int flat = p * OUTIN + i;
        int d = flat / SS, s = flat % SS;
        float v = g_x[(size_t)(b * SS + s) * DD + d];
        float xn = (v - g_mean[d]) * g_rstd[d] * bng[d] + bnb[d];
        a0 += xn * w6[i * 2 + 0];
        a1 += xn * w6[i * 2 + 1];
    }
    r0[threadIdx.x] = a0; r1[threadIdx.x] = a1; __syncthreads();
    for (int o = 64; o > 0; o >>= 1) {
        if (threadIdx.x < o) { r0[threadIdx.x] += r0[threadIdx.x + o]; r1[threadIdx.x] += r1[threadIdx.x + o]; }
        __syncthreads();
    }
    if (threadIdx.x == 0) {
        out[bp * 2 + 0] = tanhf(r0[0] + b6[0]);
        out[bp * 2 + 1] = tanhf(r1[0] + b6[1]);
    }
}

// ---------------- launch ----------------
extern "C" void kernel_launch(void* const* d_in, const int* in_sizes, int n_in,
                              void* d_out, int out_size) {
    const float* inp = (const float*)d_in[0];
    const float* Wg  = (const float*)d_in[1];
    const float* Rg  = (const float*)d_in[2];
    const float* bgp = (const float*)d_in[3];
    const float* lng = (const float*)d_in[4];
    const float* lnb = (const float*)d_in[5];
    const float* bng = (const float*)d_in[6];
    const float* bnb = (const float*)d_in[7];
    const float* w6  = (const float*)d_in[8];
    const float* b6  = (const float*)d_in[9];
    float* out = (float*)d_out;

    const int NW = 4 * DD * DD;
    k_reshape<<<(ROWS * DD + 255) / 256, 256>>>(inp);
    for (int l = 0; l < NBL; l++) {
        k_zero_state<<<(BB * DD + 255) / 256, 256>>>();
        k_convW<<<(NW + 255) / 256, 256>>>(Wg + (size_t)l * NW);
        k_convR<<<(NW + 255) / 256, 256>>>(Rg + (size_t)l * NW);
        k_layernorm<<<ROWS, 128>>>(lng + l * DD, lnb + l * DD);
        k_wgemm<<<dim3(9, 160, 4), 128>>>(bgp + (size_t)l * 4 * DD);
        for (int s = 0; s < SS; s++) {
            k_step<<<dim3(36, 4), 128>>>(s, s & 1);
        }
    }
    k_bnstats<<<DD, 256>>>();
    k_final<<<BB * PP, 128>>>(w6, b6, bng, bnb, out);
}

// round 9
// speedup vs baseline: 2.3635x; 1.4540x over previous
#include <cuda_runtime.h>

#define BB 256
#define DD 564
#define SS 40
#define PP 20
#define NBL 6
#define NCOL 2256      /* 4*DD */
#define NCOL2 1128
#define ROWS 10240     /* BB*SS */
#define OUTIN 1128
#define KPAD 576       /* 18 * 32 */
#define NKC 18
#define CBLK 36
#define BBLK 4

// ---------------- scratch (static device globals; no allocation) ----------------
__device__ float g_x[ROWS * DD];           // activations (b,s,d)
__device__ float g_pre[SS * BB * NCOL];    // (s,b, e*4+g)  gate-interleaved
__device__ float g_mean[DD];
__device__ float g_rstd[DD];
__device__ uint2 g_hsp[ROWS * DD];         // layernorm out, split tf32 {hi,lo}
__device__ uint2 g_Wsp[4 * DD * DD];       // W split, layout [g][d][e]
__device__ float g_Rhi[DD * NCOL];         // R tf32-hi, layout [d][e*4+g]
__device__ unsigned short g_Rlo[DD * NCOL];// R lo as bf16-style top16, same layout
__device__ float g_hstate[2][BB * DD];     // hidden state (plain fp32), dbl-buffered
__device__ unsigned g_bcnt[BBLK * 32];     // barrier counters (padded)
__device__ unsigned g_bgen[BBLK * 32];     // barrier generations (padded)

// ---------------- tf32 helpers ----------------
__device__ __forceinline__ unsigned f2tf(float f) {
    unsigned r;
    asm("cvt.rna.tf32.f32 %0, %1;" : "=r"(r) : "f"(f));
    return r;
}
__device__ __forceinline__ uint2 split2(float f) {
    unsigned h = f2tf(f);
    return make_uint2(h, f2tf(f - __uint_as_float(h)));
}
__device__ __forceinline__ void mma8(float* d, const unsigned* a, const unsigned* b) {
    asm volatile(
        "mma.sync.aligned.m16n8k8.row.col.f32.tf32.tf32.f32 "
        "{%0,%1,%2,%3}, {%4,%5,%6,%7}, {%8,%9}, {%0,%1,%2,%3};"
        : "+f"(d[0]), "+f"(d[1]), "+f"(d[2]), "+f"(d[3])
        : "r"(a[0]), "r"(a[1]), "r"(a[2]), "r"(a[3]), "r"(b[0]), "r"(b[1]));
}

// ---------------- input reshape: inp(b, d*S+s) -> x(b,s,d) ----------------
__global__ void k_reshape(const float* __restrict__ inp) {
    int idx = blockIdx.x * blockDim.x + threadIdx.x;
    if (idx >= ROWS * DD) return;
    int d = idx % DD;
    int r = idx / DD;
    int s = r % SS;
    int b = r / SS;
    g_x[idx] = inp[(size_t)b * (DD * SS) + d * SS + s];
}

// ---------------- per-layer weight pre-split ----------------
__global__ void k_convW(const float* __restrict__ W) {
    int i = blockIdx.x * blockDim.x + threadIdx.x;
    if (i >= 4 * DD * DD) return;
    g_Wsp[i] = split2(W[i]);
}
__global__ void k_convR(const float* __restrict__ R) {
    int i = blockIdx.x * blockDim.x + threadIdx.x;
    if (i >= 4 * DD * DD) return;
    int g = i / (DD * DD);
    int rem = i - g * DD * DD;
    int d = rem / DD;
    int e = rem - d * DD;
    float f = R[i];
    unsigned h = f2tf(f);
    float lo = f - __uint_as_float(h);
    unsigned lu = __float_as_uint(lo);
    unsigned rr = lu + 0x7fffu + ((lu >> 16) & 1u);   // RN to bf16
    int col = e * 4 + g;
    g_Rhi[(size_t)d * NCOL + col] = __uint_as_float(h);
    g_Rlo[(size_t)d * NCOL + col] = (unsigned short)(rr >> 16);
}

// ---------------- per-row layernorm over D, emits split tf32 ----------------
__global__ void k_layernorm(const float* __restrict__ lng, const float* __restrict__ lnb) {
    int row = blockIdx.x;
    const float* xr = g_x + (size_t)row * DD;
    __shared__ float red[128];
    __shared__ float s_mu, s_rs;
    float s1 = 0.f, s2 = 0.f;
    for (int d = threadIdx.x; d < DD; d += 128) { float v = xr[d]; s1 += v; s2 += v * v; }
    red[threadIdx.x] = s1; __syncthreads();
    for (int o = 64; o > 0; o >>= 1) { if (threadIdx.x < o) red[threadIdx.x] += red[threadIdx.x + o]; __syncthreads(); }
    if (threadIdx.x == 0) s_mu = red[0] / DD;
    __syncthreads();
    red[threadIdx.x] = s2; __syncthreads();
    for (int o = 64; o > 0; o >>= 1) { if (threadIdx.x < o) red[threadIdx.x] += red[threadIdx.x + o]; __syncthreads(); }
    if (threadIdx.x == 0) {
        float var = red[0] / DD - s_mu * s_mu;
        s_rs = rsqrtf(var + 1e-5f);
    }
    __syncthreads();
    float mu = s_mu, rs = s_rs;
    for (int d = threadIdx.x; d < DD; d += 128) {
        float h = (xr[d] - mu) * rs * lng[d] + lnb[d];
        g_hsp[(size_t)row * DD + d] = split2(h);
    }
}

// ---------------- W GEMM (unchanged from R8) ----------------
__global__ void __launch_bounds__(128) k_wgemm(const float* __restrict__ bias) {
    __shared__ uint2 As2[64][36];
    __shared__ uint2 Bs2[32][68];
    int g  = blockIdx.z;
    int n0 = blockIdx.x * 64;
    int m0 = blockIdx.y * 64;
    int t = threadIdx.x, lane = t & 31, wid = t >> 5;
    int wm = wid >> 1, wn = wid & 1;

    float acc[2][4][4];
#pragma unroll
    for (int i = 0; i < 2; i++)
#pragma unroll
        for (int j = 0; j < 4; j++)
#pragma unroll
            for (int k = 0; k < 4; k++) acc[i][j][k] = 0.f;

    int ar = t >> 1, akb = (t & 1) * 16;
    int bkq = t >> 2, bcq = (t & 3) * 16;
    const uint2* Asrc = g_hsp + (size_t)(m0 + ar) * DD;
    const uint2* Bsrc = g_Wsp + (size_t)g * DD * DD;

    for (int k0 = 0; k0 < KPAD; k0 += 32) {
#pragma unroll
        for (int j = 0; j < 8; j++) {
            int kk = akb + j * 2;
            int gk = k0 + kk;
            uint4 v = make_uint4(0u, 0u, 0u, 0u);
            if (gk < DD) v = *(const uint4*)(Asrc + gk);
            *(uint4*)&As2[ar][kk] = v;
        }
        {
            int gk = k0 + bkq;
            const uint2* wp = Bsrc + (size_t)gk * DD + n0;
#pragma unroll
            for (int j = 0; j < 8; j++) {
                int c = bcq + j * 2;
                int ge = n0 + c;
                uint4 v = make_uint4(0u, 0u, 0u, 0u);
                if (gk < DD && ge < DD) v = *(const uint4*)(wp + c);
                *(uint4*)&Bs2[bkq][c] = v;
            }
        }
        __syncthreads();
#pragma unroll
        for (int ks = 0; ks < 4; ks++) {
            int kk = ks * 8;
            int c = kk + (lane & 3);
            unsigned ah[2][4], al[2][4], bh[4][2], bl[4][2];
#pragma unroll
            for (int mi = 0; mi < 2; mi++) {
                int row = wm * 32 + mi * 16 + (lane >> 2);
                uint2 a00 = As2[row][c],     a01 = As2[row + 8][c];
                uint2 a10 = As2[row][c + 4], a11 = As2[row + 8][c + 4];
                ah[mi][0] = a00.x; ah[mi][1] = a01.x; ah[mi][2] = a10.x; ah[mi][3] = a11.x;
                al[mi][0] = a00.y; al[mi][1] = a01.y; al[mi][2] = a10.y; al[mi][3] = a11.y;
            }
#pragma unroll
            for (int ni = 0; ni < 4; ni++) {
                int cb = wn * 32 + ni * 8 + (lane >> 2);
                uint2 b0 = Bs2[c][cb], b1 = Bs2[c + 4][cb];
                bh[ni][0] = b0.x; bh[ni][1] = b1.x;
                bl[ni][0] = b0.y; bl[ni][1] = b1.y;
            }
#pragma unroll
            for (int mi = 0; mi < 2; mi++)
#pragma unroll
                for (int ni = 0; ni < 4; ni++) {
                    mma8(acc[mi][ni], ah[mi], bh[ni]);
                    mma8(acc[mi][ni], ah[mi], bl[ni]);
                    mma8(acc[mi][ni], al[mi], bh[ni]);
                }
        }
        __syncthreads();
    }
    const float* bp = bias + g * DD;
#pragma unroll
    for (int mi = 0; mi < 2; mi++) {
        int row0 = m0 + wm * 32 + mi * 16 + (lane >> 2);
        int row1 = row0 + 8;
        int b0r = row0 / SS, s0r = row0 - b0r * SS;
        int b1r = row1 / SS, s1r = row1 - b1r * SS;
        float* o0 = g_pre + (size_t)(s0r * BB + b0r) * NCOL + g;
        float* o1 = g_pre + (size_t)(s1r * BB + b1r) * NCOL + g;
#pragma unroll
        for (int ni = 0; ni < 4; ni++) {
            int e = n0 + wn * 32 + ni * 8 + (lane & 3) * 2;
            if (e < DD) {
                float bv0 = bp[e], bv1 = bp[e + 1];
                o0[(e) * 4]     = acc[mi][ni][0] + bv0;
                o0[(e + 1) * 4] = acc[mi][ni][1] + bv1;
                o1[(e) * 4]     = acc[mi][ni][2] + bv0;
                o1[(e + 1) * 4] = acc[mi][ni][3] + bv1;
            }
        }
    }
}

// ---------------- persistent scan kernel ----------------
// smem layout
#define SBH_SZ  (576 * 72 * 4)          /* persistent R-hi  [k576][72]   */
#define SA_SZ   (2 * 64 * 36 * 8)       /* A double buffer  uint2        */
#define SBL_SZ  (2 * 32 * 72 * 4)       /* R-lo chunk dbl   [32][72]     */
#define SCAN_SMEM (SBH_SZ + SA_SZ + SBL_SZ)   /* 221184 B */

__device__ __forceinline__ void group_barrier(int grp, unsigned target) {
    __threadfence();
    __syncthreads();
    if (threadIdx.x == 0) {
        unsigned arr = atomicAdd(&g_bcnt[grp * 32], 1u);
        if (arr == CBLK - 1u) {
            *((volatile unsigned*)&g_bcnt[grp * 32]) = 0u;
            __threadfence();
            atomicExch(&g_bgen[grp * 32], target);
        } else {
            while (*((volatile unsigned*)&g_bgen[grp * 32]) < target) __nanosleep(32);
            __threadfence();
        }
    }
    __syncthreads();
}

__global__ void __launch_bounds__(256, 1) k_scan() {
    extern __shared__ char smraw[];
    unsigned* sBh = (unsigned*)(smraw);
    uint2*    sA  = (uint2*)(smraw + SBH_SZ);
    unsigned* sBl = (unsigned*)(smraw + SBH_SZ + SA_SZ);

    int t = threadIdx.x, lane = t & 31;
    int wid = t >> 5, wm = wid >> 2, wn = wid & 3;
    int cb0 = blockIdx.x * 64;
    int b0  = blockIdx.y * 64;
    int grp = blockIdx.y;

    // ---- fill persistent R-hi tile (rows >= DD zero-padded) ----
    for (int i = t; i < 576 * 16; i += 256) {
        int k = i >> 4, c4 = (i & 15) * 4;
        int gc = cb0 + c4;
        float4 v = make_float4(0.f, 0.f, 0.f, 0.f);
        if (k < DD) {
            const float* p = g_Rhi + (size_t)k * NCOL + gc;
            if (gc + 3 < NCOL) v = *(const float4*)p;
            else {
                if (gc     < NCOL) v.x = p[0];
                if (gc + 1 < NCOL) v.y = p[1];
                if (gc + 2 < NCOL) v.z = p[2];
            }
        }
        unsigned* d = sBh + k * 72 + c4;
        d[0] = __float_as_uint(v.x); d[1] = __float_as_uint(v.y);
        d[2] = __float_as_uint(v.z); d[3] = __float_as_uint(v.w);
    }

    // ---- zero h0 for this b-group (redundant across col-blocks; benign) ----
    for (int i = t; i < 64 * DD; i += 256) g_hstate[0][b0 * DD + i] = 0.f;

    // per-thread recurrent state (live on even lanes)
    float sc[2][2][2], snr[2][2][2], smx[2][2][2];
#pragma unroll
    for (int a = 0; a < 2; a++)
#pragma unroll
        for (int b = 0; b < 2; b++)
#pragma unroll
            for (int c = 0; c < 2; c++) { sc[a][b][c] = 0.f; snr[a][b][c] = 0.f; smx[a][b][c] = 0.f; }

    unsigned target = *((volatile unsigned*)&g_bgen[grp * 32]);
    ++target; group_barrier(grp, target);

    const int ar = t >> 2, ak = (t & 3) * 8;     // A staging map
    const int kq = t >> 3, cq = (t & 7) * 4;     // Bl staging map (uint idx)
    const unsigned* RloU = (const unsigned*)g_Rlo;
    const int rloCol0 = blockIdx.x * 32;

    for (int s = 0; s < SS; s++) {
        const float* hp = g_hstate[s & 1];
        float*       hn = g_hstate[(s & 1) ^ 1];

        float acc[2][2][4];
#pragma unroll
        for (int i = 0; i < 2; i++)
#pragma unroll
            for (int j = 0; j < 2; j++)
#pragma unroll
                for (int k = 0; k < 4; k++) acc[i][j][k] = 0.f;

        float a0[4], a1[4];
        unsigned blv[4];

        // stage chunk 0 (k < 32 < DD always)
        {
            const float* ap = hp + (size_t)(b0 + ar) * DD + ak;
            *(float4*)a0 = __ldcg((const float4*)ap);
            *(float4*)a1 = __ldcg((const float4*)(ap + 4));
            const unsigned* rp = RloU + (size_t)kq * NCOL2 + rloCol0 + cq;
#pragma unroll
            for (int j = 0; j < 4; j++)
                blv[j] = (rloCol0 + cq + j < NCOL2) ? __ldg(rp + j) : 0u;
            uint2* Ad = sA + ar * 36 + ak;
#pragma unroll
            for (int j = 0; j < 4; j++) { Ad[j] = split2(a0[j]); Ad[4 + j] = split2(a1[j]); }
            unsigned* Bd = sBl + kq * 72 + cq * 2;
#pragma unroll
            for (int j = 0; j < 4; j++) { Bd[2 * j] = blv[j] << 16; Bd[2 * j + 1] = blv[j] & 0xffff0000u; }
        }
        __syncthreads();

        for (int kc = 0; kc < NKC; kc++) {
            int buf = kc & 1;
            bool more = (kc + 1 < NKC);
            if (more) {
                int k0n = (kc + 1) * 32;
                int gk = k0n + ak;
                const float* ap = hp + (size_t)(b0 + ar) * DD + gk;
                if (gk + 7 < DD) {
                    *(float4*)a0 = __ldcg((const float4*)ap);
                    *(float4*)a1 = __ldcg((const float4*)(ap + 4));
                } else {
#pragma unroll
                    for (int j = 0; j < 4; j++) {
                        a0[j] = (gk + j     < DD) ? __ldcg(ap + j)     : 0.f;
                        a1[j] = (gk + 4 + j < DD) ? __ldcg(ap + 4 + j) : 0.f;
                    }
                }
                int gkb = k0n + kq;
                if (gkb < DD) {
                    const unsigned* rp = RloU + (size_t)gkb * NCOL2 + rloCol0 + cq;
#pragma unroll
                    for (int j = 0; j < 4; j++)
                        blv[j] = (rloCol0 + cq + j < NCOL2) ? __ldg(rp + j) : 0u;
                } else {
#pragma unroll
                    for (int j = 0; j < 4; j++) blv[j] = 0u;
                }
            }
            // compute on buf
            const uint2* Ab = sA + buf * (64 * 36);
            const unsigned* Blb = sBl + buf * (32 * 72);
            int kcbase = kc * 32;
#pragma unroll
            for (int ks = 0; ks < 4; ks++) {
                int kr = ks * 8 + (lane & 3);
                unsigned ah[2][4], al[2][4];
#pragma unroll
                for (int mi = 0; mi < 2; mi++) {
                    int row = wm * 32 + mi * 16 + (lane >> 2);
                    uint2 x00 = Ab[row * 36 + kr];
                    uint2 x01 = Ab[(row + 8) * 36 + kr];
                    uint2 x10 = Ab[row * 36 + kr + 4];
                    uint2 x11 = Ab[(row + 8) * 36 + kr + 4];
                    ah[mi][0] = x00.x; ah[mi][1] = x01.x; ah[mi][2] = x10.x; ah[mi][3] = x11.x;
                    al[mi][0] = x00.y; al[mi][1] = x01.y; al[mi][2] = x10.y; al[mi][3] = x11.y;
                }
#pragma unroll
                for (int ni = 0; ni < 2; ni++) {
                    int cb = wn * 16 + ni * 8 + (lane >> 2);
                    unsigned bh[2], bl[2];
                    bh[0] = sBh[(kcbase + kr) * 72 + cb];
                    bh[1] = sBh[(kcbase + kr + 4) * 72 + cb];
                    bl[0] = Blb[kr * 72 + cb];
                    bl[1] = Blb[(kr + 4) * 72 + cb];
#pragma unroll
                    for (int mi = 0; mi < 2; mi++) {
                        mma8(acc[mi][ni], ah[mi], bh);
                        mma8(acc[mi][ni], al[mi], bh);
                        mma8(acc[mi][ni], ah[mi], bl);
                    }
                }
            }
            if (more) {
                uint2* Ad = sA + (buf ^ 1) * (64 * 36) + ar * 36 + ak;
#pragma unroll
                for (int j = 0; j < 4; j++) { Ad[j] = split2(a0[j]); Ad[4 + j] = split2(a1[j]); }
                unsigned* Bd = sBl + (buf ^ 1) * (32 * 72) + kq * 72 + cq * 2;
#pragma unroll
                for (int j = 0; j < 4; j++) { Bd[2 * j] = blv[j] << 16; Bd[2 * j + 1] = blv[j] & 0xffff0000u; }
            }
            __syncthreads();
        }

        // ---- fused sLSTM epilogue (state in regs) ----
#pragma unroll
        for (int mi = 0; mi < 2; mi++) {
            int br = b0 + wm * 32 + mi * 16 + (lane >> 2);
#pragma unroll
            for (int ni = 0; ni < 2; ni++) {
                float d0 = acc[mi][ni][0], d1 = acc[mi][ni][1];
                float d2 = acc[mi][ni][2], d3 = acc[mi][ni][3];
                float p0 = __shfl_xor_sync(0xffffffffu, d0, 1);
                float p1 = __shfl_xor_sync(0xffffffffu, d1, 1);
                float p2 = __shfl_xor_sync(0xffffffffu, d2, 1);
                float p3 = __shfl_xor_sync(0xffffffffu, d3, 1);
                if ((lane & 1) == 0) {
                    int c = cb0 + wn * 16 + ni * 8 + (lane & 3) * 2;
                    if (c < NCOL) {
                        int e = c >> 2;
#pragma unroll
                        for (int rr = 0; rr < 2; rr++) {
                            int bb = br + rr * 8;
                            float4 pr = *(const float4*)(g_pre + (size_t)(s * BB + bb) * NCOL + c);
                            float it = (rr ? d2 : d0) + pr.x;
                            float ft = (rr ? d3 : d1) + pr.y;
                            float zt = (rr ? p2 : p0) + pr.z;
                            float ot = (rr ? p3 : p1) + pr.w;
                            float mo = smx[mi][ni][rr];
                            float mn = fmaxf(ft + mo, it);
                            float iv = expf(it - mn);
                            float fv = expf(ft + mo - mn);
                            float cn = fv * sc[mi][ni][rr] + iv * tanhf(zt);
                            float nn = fv * snr[mi][ni][rr] + iv;
                            float sg = 1.f / (1.f + expf(-ot));
                            float hv = sg * cn / fmaxf(nn, 1e-6f);
                            sc[mi][ni][rr] = cn; snr[mi][ni][rr] = nn; smx[mi][ni][rr] = mn;
                            hn[bb * DD + e] = hv;
                            g_x[(size_t)(bb * SS + s) * DD + e] += hv;
                        }
                    }
                }
            }
        }
        ++target; group_barrier(grp, target);
    }
}

// ---------------- batchnorm statistics: per-d over (b,s) ----------------
__global__ void k_bnstats() {
    int d = blockIdx.x;
    __shared__ float r1[256], r2[256];
    float s1 = 0.f, s2 = 0.f;
    for (int r = threadIdx.x; r < ROWS; r += 256) {
        float v = g_x[(size_t)r * DD + d];
        s1 += v; s2 += v * v;
    }
    r1[threadIdx.x] = s1; r2[threadIdx.x] = s2; __syncthreads();
    for (int o = 128; o > 0; o >>= 1) {
        if (threadIdx.x < o) { r1[threadIdx.x] += r1[threadIdx.x + o]; r2[threadIdx.x] += r2[threadIdx.x + o]; }
        __syncthreads();
    }
    if (threadIdx.x == 0) {
        float mu = r1[0] / (float)ROWS;
        float var = r2[0] / (float)ROWS - mu * mu;
        g_mean[d] = mu;
        g_rstd[d] = rsqrtf(var + 1e-5f);
    }
}

// ---------------- final: bn-normalize, reshape (B,P,1128), @ w6, tanh ----------------
__global__ void k_final(const float* __restrict__ w6, const float* __restrict__ b6,
                        const float* __restrict__ bng, const float* __restrict__ bnb,
                        float* __restrict__ out) {
    int bp = blockIdx.x;
    int b = bp / PP, p = bp % PP;
    __shared__ float r0[128], r1[128];
    float a0 = 0.f, a1 = 0.f;
    for (int i = threadIdx.x; i < OUTIN; i += 128) {
        int flat = p * OUTIN + i;
        int d = flat / SS, s = flat % SS;
        float v = g_x[(size_t)(b * SS + s) * DD + d];
        float xn = (v - g_mean[d]) * g_rstd[d] * bng[d] + bnb[d];
        a0 += xn * w6[i * 2 + 0];
        a1 += xn * w6[i * 2 + 1];
    }
    r0[threadIdx.x] = a0; r1[threadIdx.x] = a1; __syncthreads();
    for (int o = 64; o > 0; o >>= 1) {
        if (threadIdx.x < o) { r0[threadIdx.x] += r0[threadIdx.x + o]; r1[threadIdx.x] += r1[threadIdx.x + o]; }
        __syncthreads();
    }
    if (threadIdx.x == 0) {
        out[bp * 2 + 0] = tanhf(r0[0] + b6[0]);
        out[bp * 2 + 1] = tanhf(r1[0] + b6[1]);
    }
}

// ---------------- launch ----------------
extern "C" void kernel_launch(void* const* d_in, const int* in_sizes, int n_in,
                              void* d_out, int out_size) {
    const float* inp = (const float*)d_in[0];
    const float* Wg  = (const float*)d_in[1];
    const float* Rg  = (const float*)d_in[2];
    const float* bgp = (const float*)d_in[3];
    const float* lng = (const float*)d_in[4];
    const float* lnb = (const float*)d_in[5];
    const float* bng = (const float*)d_in[6];
    const float* bnb = (const float*)d_in[7];
    const float* w6  = (const float*)d_in[8];
    const float* b6  = (const float*)d_in[9];
    float* out = (float*)d_out;

    cudaFuncSetAttribute(k_scan, cudaFuncAttributeMaxDynamicSharedMemorySize, SCAN_SMEM);

    const int NW = 4 * DD * DD;
    k_reshape<<<(ROWS * DD + 255) / 256, 256>>>(inp);
    for (int l = 0; l < NBL; l++) {
        k_convW<<<(NW + 255) / 256, 256>>>(Wg + (size_t)l * NW);
        k_convR<<<(NW + 255) / 256, 256>>>(Rg + (size_t)l * NW);
        k_layernorm<<<ROWS, 128>>>(lng + l * DD, lnb + l * DD);
        k_wgemm<<<dim3(9, 160, 4), 128>>>(bgp + (size_t)l * 4 * DD);
        k_scan<<<dim3(CBLK, BBLK), 256, SCAN_SMEM>>>();
    }
    k_bnstats<<<DD, 256>>>();
    k_final<<<BB * PP, 128>>>(w6, b6, bng, bnb, out);
}

// round 10
// speedup vs baseline: 4.1714x; 1.7649x over previous
#include <cuda_runtime.h>
#include <cuda_fp16.h>

#define BB 256
#define DD 564
#define SS 40
#define PP 20
#define NBL 6
#define NCOL 2256      /* 4*DD */
#define ROWS 10240     /* BB*SS */
#define OUTIN 1128
#define NKC 18         /* k-chunks of 32 */
#define KP 288         /* padded k-pairs (576/2) */
#define CBLK 36
#define BBLK 4

// ---------------- scratch (static device globals; no allocation) ----------------
__device__ float g_x[ROWS * DD];           // activations (b,s,d)
__device__ float g_pre[SS * BB * NCOL];    // (s,b, e*4+g)  gate-interleaved
__device__ float g_mean[DD];
__device__ float g_rstd[DD];
__device__ float g_hstate[2][BB * DD];     // hidden state fp32, dbl-buffered
__device__ unsigned g_bcnt[BBLK * 32];
__device__ unsigned g_bgen[BBLK * 32];
// fp16-split packed operands: uint2 = {hi2 (k,k+1), lo2 (k,k+1)}
__device__ uint2 g_h16[ROWS * KP];         // layernorm out   23.6 MB
__device__ uint2 g_W16[4 * KP * DD];       // W  [g][kp][e]    5.2 MB
__device__ uint2 g_R16[KP * NCOL];         // R  [kp][e*4+g]   5.2 MB

// ---------------- fp16 split helpers ----------------
__device__ __forceinline__ uint2 pack_split(float x0, float x1) {
    __half h0 = __float2half_rn(x0), h1 = __float2half_rn(x1);
    __half l0 = __float2half_rn(x0 - __half2float(h0));
    __half l1 = __float2half_rn(x1 - __half2float(h1));
    uint2 r;
    r.x = (unsigned)__half_as_ushort(h0) | ((unsigned)__half_as_ushort(h1) << 16);
    r.y = (unsigned)__half_as_ushort(l0) | ((unsigned)__half_as_ushort(l1) << 16);
    return r;
}
__device__ __forceinline__ void mma16(float* d, const unsigned* a, const unsigned* b) {
    asm volatile(
        "mma.sync.aligned.m16n8k16.row.col.f32.f16.f16.f32 "
        "{%0,%1,%2,%3}, {%4,%5,%6,%7}, {%8,%9}, {%0,%1,%2,%3};"
        : "+f"(d[0]), "+f"(d[1]), "+f"(d[2]), "+f"(d[3])
        : "r"(a[0]), "r"(a[1]), "r"(a[2]), "r"(a[3]), "r"(b[0]), "r"(b[1]));
}

// ---------------- input reshape ----------------
__global__ void k_reshape(const float* __restrict__ inp) {
    int idx = blockIdx.x * blockDim.x + threadIdx.x;
    if (idx >= ROWS * DD) return;
    int d = idx % DD;
    int r = idx / DD;
    int s = r % SS;
    int b = r / SS;
    g_x[idx] = inp[(size_t)b * (DD * SS) + d * SS + s];
}

// ---------------- weight conversion (per layer) ----------------
__global__ void k_convW(const float* __restrict__ W) {
    int idx = blockIdx.x * blockDim.x + threadIdx.x;
    if (idx >= 4 * KP * DD) return;
    int g = idx / (KP * DD);
    int rem = idx - g * KP * DD;
    int kp = rem / DD;
    int e  = rem - kp * DD;
    int d0 = kp * 2, d1 = d0 + 1;
    float x0 = (d0 < DD) ? W[(size_t)g * DD * DD + (size_t)d0 * DD + e] : 0.f;
    float x1 = (d1 < DD) ? W[(size_t)g * DD * DD + (size_t)d1 * DD + e] : 0.f;
    g_W16[idx] = pack_split(x0, x1);
}
__global__ void k_convR(const float* __restrict__ R) {
    int idx = blockIdx.x * blockDim.x + threadIdx.x;
    if (idx >= KP * NCOL) return;
    int kp  = idx / NCOL;
    int col = idx - kp * NCOL;
    int e = col >> 2, g = col & 3;
    int d0 = kp * 2, d1 = d0 + 1;
    float x0 = (d0 < DD) ? R[(size_t)g * DD * DD + (size_t)d0 * DD + e] : 0.f;
    float x1 = (d1 < DD) ? R[(size_t)g * DD * DD + (size_t)d1 * DD + e] : 0.f;
    g_R16[idx] = pack_split(x0, x1);
}

// ---------------- layernorm: emits split/packed h ----------------
__global__ void k_layernorm(const float* __restrict__ lng, const float* __restrict__ lnb) {
    int row = blockIdx.x;
    const float* xr = g_x + (size_t)row * DD;
    __shared__ float red[128];
    __shared__ float s_mu, s_rs;
    float s1 = 0.f, s2 = 0.f;
    for (int d = threadIdx.x; d < DD; d += 128) { float v = xr[d]; s1 += v; s2 += v * v; }
    red[threadIdx.x] = s1; __syncthreads();
    for (int o = 64; o > 0; o >>= 1) { if (threadIdx.x < o) red[threadIdx.x] += red[threadIdx.x + o]; __syncthreads(); }
    if (threadIdx.x == 0) s_mu = red[0] / DD;
    __syncthreads();
    red[threadIdx.x] = s2; __syncthreads();
    for (int o = 64; o > 0; o >>= 1) { if (threadIdx.x < o) red[threadIdx.x] += red[threadIdx.x + o]; __syncthreads(); }
    if (threadIdx.x == 0) {
        float var = red[0] / DD - s_mu * s_mu;
        s_rs = rsqrtf(var + 1e-5f);
    }
    __syncthreads();
    float mu = s_mu, rs = s_rs;
    for (int kp = threadIdx.x; kp < KP; kp += 128) {
        int d0 = kp * 2, d1 = d0 + 1;
        float x0 = (d0 < DD) ? (xr[d0] - mu) * rs * lng[d0] + lnb[d0] : 0.f;
        float x1 = (d1 < DD) ? (xr[d1] - mu) * rs * lng[d1] + lnb[d1] : 0.f;
        g_h16[(size_t)row * KP + kp] = pack_split(x0, x1);
    }
}

// ---------------- W GEMM, fp16 3-split m16n8k16 ----------------
// Block 64m x 64n, 128 thr, warps 2x2, warp 32x32. grid (9, 160, 4)
__global__ void __launch_bounds__(128) k_wgemm(const float* __restrict__ bias) {
    __shared__ uint2 sA[64 * 20];   // [row][kp0..15], stride 20
    __shared__ uint2 sB[16 * 68];   // [kp][e0..63],   stride 68
    int g  = blockIdx.z;
    int n0 = blockIdx.x * 64;
    int m0 = blockIdx.y * 64;
    int t = threadIdx.x, lane = t & 31, wid = t >> 5;
    int wm = wid >> 1, wn = wid & 1;

    float acc[2][4][4];
#pragma unroll
    for (int i = 0; i < 2; i++)
#pragma unroll
        for (int j = 0; j < 4; j++)
#pragma unroll
            for (int k = 0; k < 4; k++) acc[i][j][k] = 0.f;

    const uint2* Wbase = g_W16 + (size_t)g * KP * DD;

    for (int kc = 0; kc < NKC; kc++) {
        { // A: rows m0..m0+63, kpairs kc*16..+15 (direct copy, pre-split)
            int row = t >> 1, kb = (t & 1) * 8;
            const uint2* src = g_h16 + (size_t)(m0 + row) * KP + kc * 16 + kb;
            uint2* dst = sA + row * 20 + kb;
            *(uint4*)(dst)     = *(const uint4*)(src);
            *(uint4*)(dst + 2) = *(const uint4*)(src + 2);
            *(uint4*)(dst + 4) = *(const uint4*)(src + 4);
            *(uint4*)(dst + 6) = *(const uint4*)(src + 6);
        }
        { // B: kpairs kc*16..+15, cols n0..n0+63
#pragma unroll
            for (int it = 0; it < 8; it++) {
                int i = t + it * 128;
                int kpr = i >> 6, c = i & 63;
                int ge = n0 + c;
                uint2 v = make_uint2(0u, 0u);
                if (ge < DD) v = Wbase[(size_t)(kc * 16 + kpr) * DD + ge];
                sB[kpr * 68 + c] = v;
            }
        }
        __syncthreads();
#pragma unroll
        for (int ts = 0; ts < 2; ts++) {
            int kpf = ts * 8 + (lane & 3);
            unsigned ah[2][4], al[2][4];
#pragma unroll
            for (int mi = 0; mi < 2; mi++) {
                int row = wm * 32 + mi * 16 + (lane >> 2);
                const uint2* Ap = sA + row * 20;
                uint2 x0 = Ap[kpf], x1 = Ap[160 + kpf];
                uint2 x2 = Ap[kpf + 4], x3 = Ap[160 + kpf + 4];
                ah[mi][0] = x0.x; ah[mi][1] = x1.x; ah[mi][2] = x2.x; ah[mi][3] = x3.x;
                al[mi][0] = x0.y; al[mi][1] = x1.y; al[mi][2] = x2.y; al[mi][3] = x3.y;
            }
#pragma unroll
            for (int ni = 0; ni < 4; ni++) {
                int cb = wn * 32 + ni * 8 + (lane >> 2);
                uint2 b0 = sB[kpf * 68 + cb];
                uint2 b1 = sB[(kpf + 4) * 68 + cb];
                unsigned bh[2] = {b0.x, b1.x};
                unsigned bl[2] = {b0.y, b1.y};
#pragma unroll
                for (int mi = 0; mi < 2; mi++) {
                    mma16(acc[mi][ni], ah[mi], bh);
                    mma16(acc[mi][ni], ah[mi], bl);
                    mma16(acc[mi][ni], al[mi], bh);
                }
            }
        }
        __syncthreads();
    }
    const float* bp = bias + g * DD;
#pragma unroll
    for (int mi = 0; mi < 2; mi++) {
        int row0 = m0 + wm * 32 + mi * 16 + (lane >> 2);
        int row1 = row0 + 8;
        int b0r = row0 / SS, s0r = row0 - b0r * SS;
        int b1r = row1 / SS, s1r = row1 - b1r * SS;
        float* o0 = g_pre + (size_t)(s0r * BB + b0r) * NCOL + g;
        float* o1 = g_pre + (size_t)(s1r * BB + b1r) * NCOL + g;
#pragma unroll
        for (int ni = 0; ni < 4; ni++) {
            int e = n0 + wn * 32 + ni * 8 + (lane & 3) * 2;
            if (e < DD) {
                float bv0 = bp[e], bv1 = bp[e + 1];
                o0[(e) * 4]     = acc[mi][ni][0] + bv0;
                o0[(e + 1) * 4] = acc[mi][ni][1] + bv1;
                o1[(e) * 4]     = acc[mi][ni][2] + bv0;
                o1[(e + 1) * 4] = acc[mi][ni][3] + bv1;
            }
        }
    }
}

// ---------------- persistent scan ----------------
#define SB_SZ (KP * 68 * 8)            /* 156672: R hi+lo persistent */
#define SA_SZ (2 * 64 * 20 * 8)        /* 20480:  A double buffer    */
#define SCAN_SMEM (SB_SZ + SA_SZ)      /* 177152 */

__device__ __forceinline__ void group_barrier(int grp, unsigned target) {
    __threadfence();
    __syncthreads();
    if (threadIdx.x == 0) {
        unsigned arr = atomicAdd(&g_bcnt[grp * 32], 1u);
        if (arr == CBLK - 1u) {
            *((volatile unsigned*)&g_bcnt[grp * 32]) = 0u;
            __threadfence();
            atomicExch(&g_bgen[grp * 32], target);
        } else {
            while (*((volatile unsigned*)&g_bgen[grp * 32]) < target) __nanosleep(32);
            __threadfence();
        }
    }
    __syncthreads();
}

__global__ void __launch_bounds__(256, 1) k_scan() {
    extern __shared__ char smraw[];
    uint2* sB = (uint2*)smraw;                 // [kp][c], stride 68
    uint2* sA = (uint2*)(smraw + SB_SZ);       // 2 x [row][kp], stride 20

    int t = threadIdx.x, lane = t & 31;
    int wid = t >> 5, wm = wid >> 2, wn = wid & 3;
    int cb0 = blockIdx.x * 64;
    int b0  = blockIdx.y * 64;
    int grp = blockIdx.y;

    // fill persistent R tile (hi+lo)
    for (int i = t; i < KP * 64; i += 256) {
        int kp = i >> 6, c = i & 63;
        int gc = cb0 + c;
        uint2 v = make_uint2(0u, 0u);
        if (gc < NCOL) v = g_R16[(size_t)kp * NCOL + gc];
        sB[kp * 68 + c] = v;
    }

    // zero h0 for this b-group (redundant across col-blocks; benign)
    for (int i = t; i < 64 * DD; i += 256) g_hstate[0][b0 * DD + i] = 0.f;

    float sc[2][2][2], snr[2][2][2], smx[2][2][2];
#pragma unroll
    for (int a = 0; a < 2; a++)
#pragma unroll
        for (int b = 0; b < 2; b++)
#pragma unroll
            for (int c = 0; c < 2; c++) { sc[a][b][c] = 0.f; snr[a][b][c] = 0.f; smx[a][b][c] = 0.f; }

    unsigned target = *((volatile unsigned*)&g_bgen[grp * 32]);
    ++target; group_barrier(grp, target);

    const int ar = t >> 2, akb = (t & 3) * 4;   // A staging: row, kpair base

    for (int s = 0; s < SS; s++) {
        const float* hp = g_hstate[s & 1];
        float*       hn = g_hstate[(s & 1) ^ 1];

        float acc[2][2][4];
#pragma unroll
        for (int i = 0; i < 2; i++)
#pragma unroll
            for (int j = 0; j < 2; j++)
#pragma unroll
                for (int k = 0; k < 4; k++) acc[i][j][k] = 0.f;

        float a0[4], a1[4];

        { // stage chunk 0 (k = akb*2 .. akb*2+7 < 32 < DD)
            const float* ap = hp + (size_t)(b0 + ar) * DD + akb * 2;
            *(float4*)a0 = __ldcg((const float4*)ap);
            *(float4*)a1 = __ldcg((const float4*)(ap + 4));
            uint2* Ad = sA + ar * 20 + akb;
            Ad[0] = pack_split(a0[0], a0[1]);
            Ad[1] = pack_split(a0[2], a0[3]);
            Ad[2] = pack_split(a1[0], a1[1]);
            Ad[3] = pack_split(a1[2], a1[3]);
        }
        __syncthreads();

        for (int kc = 0; kc < NKC; kc++) {
            int buf = kc & 1;
            bool more = (kc + 1 < NKC);
            if (more) {
                int gk = (kc + 1) * 32 + akb * 2;
                const float* ap = hp + (size_t)(b0 + ar) * DD + gk;
                if (gk + 7 < DD) {
                    *(float4*)a0 = __ldcg((const float4*)ap);
                    *(float4*)a1 = __ldcg((const float4*)(ap + 4));
                } else {
#pragma unroll
                    for (int j = 0; j < 4; j++) {
                        a0[j] = (gk + j     < DD) ? __ldcg(ap + j)     : 0.f;
                        a1[j] = (gk + 4 + j < DD) ? __ldcg(ap + 4 + j) : 0.f;
                    }
                }
            }
            const uint2* Ab = sA + buf * (64 * 20);
            int kpc = kc * 16;
#pragma unroll
            for (int ts = 0; ts < 2; ts++) {
                int kpl = ts * 8 + (lane & 3);
                unsigned ah[2][4], al[2][4];
#pragma unroll
                for (int mi = 0; mi < 2; mi++) {
                    int row = wm * 32 + mi * 16 + (lane >> 2);
                    const uint2* Ap = Ab + row * 20;
                    uint2 x0 = Ap[kpl], x1 = Ap[160 + kpl];
                    uint2 x2 = Ap[kpl + 4], x3 = Ap[160 + kpl + 4];
                    ah[mi][0] = x0.x; ah[mi][1] = x1.x; ah[mi][2] = x2.x; ah[mi][3] = x3.x;
                    al[mi][0] = x0.y; al[mi][1] = x1.y; al[mi][2] = x2.y; al[mi][3] = x3.y;
                }
#pragma unroll
                for (int ni = 0; ni < 2; ni++) {
                    int cb = wn * 16 + ni * 8 + (lane >> 2);
                    int kpf = kpc + kpl;
                    uint2 b0v = sB[kpf * 68 + cb];
                    uint2 b1v = sB[(kpf + 4) * 68 + cb];
                    unsigned bh[2] = {b0v.x, b1v.x};
                    unsigned bl[2] = {b0v.y, b1v.y};
#pragma unroll
                    for (int mi = 0; mi < 2; mi++) {
                        mma16(acc[mi][ni], ah[mi], bh);
                        mma16(acc[mi][ni], ah[mi], bl);
                        mma16(acc[mi][ni], al[mi], bh);
                    }
                }
            }
            if (more) {
                uint2* Ad = sA + (buf ^ 1) * (64 * 20) + ar * 20 + akb;
                Ad[0] = pack_split(a0[0], a0[1]);
                Ad[1] = pack_split(a0[2], a0[3]);
                Ad[2] = pack_split(a1[0], a1[1]);
                Ad[3] = pack_split(a1[2], a1[3]);
            }
            __syncthreads();
        }

        // fused sLSTM epilogue (state in regs)
#pragma unroll
        for (int mi = 0; mi < 2; mi++) {
            int br = b0 + wm * 32 + mi * 16 + (lane >> 2);
#pragma unroll
            for (int ni = 0; ni < 2; ni++) {
                float d0 = acc[mi][ni][0], d1 = acc[mi][ni][1];
                float d2 = acc[mi][ni][2], d3 = acc[mi][ni][3];
                float p0 = __shfl_xor_sync(0xffffffffu, d0, 1);
                float p1 = __shfl_xor_sync(0xffffffffu, d1, 1);
                float p2 = __shfl_xor_sync(0xffffffffu, d2, 1);
                float p3 = __shfl_xor_sync(0xffffffffu, d3, 1);
                if ((lane & 1) == 0) {
                    int c = cb0 + wn * 16 + ni * 8 + (lane & 3) * 2;
                    if (c < NCOL) {
                        int e = c >> 2;
#pragma unroll
                        for (int rr = 0; rr < 2; rr++) {
                            int bb = br + rr * 8;
                            float4 pr = *(const float4*)(g_pre + (size_t)(s * BB + bb) * NCOL + c);
                            float it = (rr ? d2 : d0) + pr.x;
                            float ft = (rr ? d3 : d1) + pr.y;
                            float zt = (rr ? p2 : p0) + pr.z;
                            float ot = (rr ? p3 : p1) + pr.w;
                            float mo = smx[mi][ni][rr];
                            float mn = fmaxf(ft + mo, it);
                            float iv = expf(it - mn);
                            float fv = expf(ft + mo - mn);
                            float cn = fv * sc[mi][ni][rr] + iv * tanhf(zt);
                            float nn = fv * snr[mi][ni][rr] + iv;
                            float sg = 1.f / (1.f + expf(-ot));
                            float hv = sg * cn / fmaxf(nn, 1e-6f);
                            sc[mi][ni][rr] = cn; snr[mi][ni][rr] = nn; smx[mi][ni][rr] = mn;
                            hn[bb * DD + e] = hv;
                            g_x[(size_t)(bb * SS + s) * DD + e] += hv;
                        }
                    }
                }
            }
        }
        ++target; group_barrier(grp, target);
    }
}

// ---------------- batchnorm statistics ----------------
__global__ void k_bnstats() {
    int d = blockIdx.x;
    __shared__ float r1[256], r2[256];
    float s1 = 0.f, s2 = 0.f;
    for (int r = threadIdx.x; r < ROWS; r += 256) {
        float v = g_x[(size_t)r * DD + d];
        s1 += v; s2 += v * v;
    }
    r1[threadIdx.x] = s1; r2[threadIdx.x] = s2; __syncthreads();
    for (int o = 128; o > 0; o >>= 1) {
        if (threadIdx.x < o) { r1[threadIdx.x] += r1[threadIdx.x + o]; r2[threadIdx.x] += r2[threadIdx.x + o]; }
        __syncthreads();
    }
    if (threadIdx.x == 0) {
        float mu = r1[0] / (float)ROWS;
        float var = r2[0] / (float)ROWS - mu * mu;
        g_mean[d] = mu;
        g_rstd[d] = rsqrtf(var + 1e-5f);
    }
}

// ---------------- final projection ----------------
__global__ void k_final(const float* __restrict__ w6, const float* __restrict__ b6,
                        const float* __restrict__ bng, const float* __restrict__ bnb,
                        float* __restrict__ out) {
    int bp = blockIdx.x;
    int b = bp / PP, p = bp % PP;
    __shared__ float r0[128], r1[128];
    float a0 = 0.f, a1 = 0.f;
    for (int i = threadIdx.x; i < OUTIN; i += 128) {
        int flat = p * OUTIN + i;
        int d = flat / SS, s = flat % SS;
        float v = g_x[(size_t)(b * SS + s) * DD + d];
        float xn = (v - g_mean[d]) * g_rstd[d] * bng[d] + bnb[d];
        a0 += xn * w6[i * 2 + 0];
        a1 += xn * w6[i * 2 + 1];
    }
    r0[threadIdx.x] = a0; r1[threadIdx.x] = a1; __syncthreads();
    for (int o = 64; o > 0; o >>= 1) {
        if (threadIdx.x < o) { r0[threadIdx.x] += r0[threadIdx.x + o]; r1[threadIdx.x] += r1[threadIdx.x + o]; }
        __syncthreads();
    }
    if (threadIdx.x == 0) {
        out[bp * 2 + 0] = tanhf(r0[0] + b6[0]);
        out[bp * 2 + 1] = tanhf(r1[0] + b6[1]);
    }
}

// ---------------- launch ----------------
extern "C" void kernel_launch(void* const* d_in, const int* in_sizes, int n_in,
                              void* d_out, int out_size) {
    const float* inp = (const float*)d_in[0];
    const float* Wg  = (const float*)d_in[1];
    const float* Rg  = (const float*)d_in[2];
    const float* bgp = (const float*)d_in[3];
    const float* lng = (const float*)d_in[4];
    const float* lnb = (const float*)d_in[5];
    const float* bng = (const float*)d_in[6];
    const float* bnb = (const float*)d_in[7];
    const float* w6  = (const float*)d_in[8];
    const float* b6  = (const float*)d_in[9];
    float* out = (float*)d_out;

    cudaFuncSetAttribute(k_scan, cudaFuncAttributeMaxDynamicSharedMemorySize, SCAN_SMEM);

    const int NWQ = 4 * KP * DD;      // conv grid
    k_reshape<<<(ROWS * DD + 255) / 256, 256>>>(inp);
    for (int l = 0; l < NBL; l++) {
        k_convW<<<(NWQ + 255) / 256, 256>>>(Wg + (size_t)l * 4 * DD * DD);
        k_convR<<<(KP * NCOL + 255) / 256, 256>>>(Rg + (size_t)l * 4 * DD * DD);
        k_layernorm<<<ROWS, 128>>>(lng + l * DD, lnb + l * DD);
        k_wgemm<<<dim3(9, 160, 4), 128>>>(bgp + (size_t)l * 4 * DD);
        k_scan<<<dim3(CBLK, BBLK), 256, SCAN_SMEM>>>();
    }
    k_bnstats<<<DD, 256>>>();
    k_final<<<BB * PP, 128>>>(w6, b6, bng, bnb, out);
}

// round 11
// speedup vs baseline: 4.3318x; 1.0385x over previous
#include <cuda_runtime.h>
#include <cuda_fp16.h>

#define BB 256
#define DD 564
#define SS 40
#define PP 20
#define NBL 6
#define NCOL 2256      /* 4*DD */
#define ROWS 10240     /* BB*SS */
#define OUTIN 1128
#define KP 288         /* padded k-pairs (576/2) */
#define NKC9 9         /* k-chunks of 32 kp */
#define NKCW 18        /* wgemm k-chunks of 16 kp */
#define CBLK 36
#define BBLK 4

// ---------------- scratch (static device globals; no allocation) ----------------
__device__ float g_x[ROWS * DD];           // activations (b,s,d)
__device__ float g_pre[SS * BB * NCOL];    // (s,b, e*4+g)  gate-interleaved
__device__ float g_mean[DD];
__device__ float g_rstd[DD];
__device__ unsigned g_bcnt[BBLK * 32];
__device__ unsigned g_bgen[BBLK * 32];
// fp16-split packed operands: uint2 = {hi2 (k,k+1), lo2 (k,k+1)}
__device__ uint2 g_h16[ROWS * KP];         // layernorm out
__device__ uint2 g_W16[4 * KP * DD];       // W  [g][kp][e]
__device__ uint2 g_R16[KP * NCOL];         // R  [kp][e*4+g]
__device__ uint2 g_h16s[2][BB * KP];       // scan hidden state, split+packed, dbl-buf

// ---------------- fp16 split helpers ----------------
__device__ __forceinline__ uint2 pack_split(float x0, float x1) {
    __half h0 = __float2half_rn(x0), h1 = __float2half_rn(x1);
    __half l0 = __float2half_rn(x0 - __half2float(h0));
    __half l1 = __float2half_rn(x1 - __half2float(h1));
    uint2 r;
    r.x = (unsigned)__half_as_ushort(h0) | ((unsigned)__half_as_ushort(h1) << 16);
    r.y = (unsigned)__half_as_ushort(l0) | ((unsigned)__half_as_ushort(l1) << 16);
    return r;
}
__device__ __forceinline__ void mma16(float* d, const unsigned* a, const unsigned* b) {
    asm volatile(
        "mma.sync.aligned.m16n8k16.row.col.f32.f16.f16.f32 "
        "{%0,%1,%2,%3}, {%4,%5,%6,%7}, {%8,%9}, {%0,%1,%2,%3};"
        : "+f"(d[0]), "+f"(d[1]), "+f"(d[2]), "+f"(d[3])
        : "r"(a[0]), "r"(a[1]), "r"(a[2]), "r"(a[3]), "r"(b[0]), "r"(b[1]));
}
__device__ __forceinline__ void cpasync16(unsigned dst, const void* src) {
    asm volatile("cp.async.cg.shared.global [%0], [%1], 16;" :: "r"(dst), "l"(src));
}
__device__ __forceinline__ void cpasync_commit() {
    asm volatile("cp.async.commit_group;");
}
template <int N>
__device__ __forceinline__ void cpasync_wait() {
    asm volatile("cp.async.wait_group %0;" :: "n"(N));
}

// ---------------- input reshape ----------------
__global__ void k_reshape(const float* __restrict__ inp) {
    int idx = blockIdx.x * blockDim.x + threadIdx.x;
    if (idx >= ROWS * DD) return;
    int d = idx % DD;
    int r = idx / DD;
    int s = r % SS;
    int b = r / SS;
    g_x[idx] = inp[(size_t)b * (DD * SS) + d * SS + s];
}

// ---------------- weight conversion (per layer) ----------------
__global__ void k_convW(const float* __restrict__ W) {
    int idx = blockIdx.x * blockDim.x + threadIdx.x;
    if (idx >= 4 * KP * DD) return;
    int g = idx / (KP * DD);
    int rem = idx - g * KP * DD;
    int kp = rem / DD;
    int e  = rem - kp * DD;
    int d0 = kp * 2, d1 = d0 + 1;
    float x0 = (d0 < DD) ? W[(size_t)g * DD * DD + (size_t)d0 * DD + e] : 0.f;
    float x1 = (d1 < DD) ? W[(size_t)g * DD * DD + (size_t)d1 * DD + e] : 0.f;
    g_W16[idx] = pack_split(x0, x1);
}
__global__ void k_convR(const float* __restrict__ R) {
    int idx = blockIdx.x * blockDim.x + threadIdx.x;
    if (idx >= KP * NCOL) return;
    int kp  = idx / NCOL;
    int col = idx - kp * NCOL;
    int e = col >> 2, g = col & 3;
    int d0 = kp * 2, d1 = d0 + 1;
    float x0 = (d0 < DD) ? R[(size_t)g * DD * DD + (size_t)d0 * DD + e] : 0.f;
    float x1 = (d1 < DD) ? R[(size_t)g * DD * DD + (size_t)d1 * DD + e] : 0.f;
    g_R16[idx] = pack_split(x0, x1);
}

// ---------------- layernorm: emits split/packed h ----------------
__global__ void k_layernorm(const float* __restrict__ lng, const float* __restrict__ lnb) {
    int row = blockIdx.x;
    const float* xr = g_x + (size_t)row * DD;
    __shared__ float red[128];
    __shared__ float s_mu, s_rs;
    float s1 = 0.f, s2 = 0.f;
    for (int d = threadIdx.x; d < DD; d += 128) { float v = xr[d]; s1 += v; s2 += v * v; }
    red[threadIdx.x] = s1; __syncthreads();
    for (int o = 64; o > 0; o >>= 1) { if (threadIdx.x < o) red[threadIdx.x] += red[threadIdx.x + o]; __syncthreads(); }
    if (threadIdx.x == 0) s_mu = red[0] / DD;
    __syncthreads();
    red[threadIdx.x] = s2; __syncthreads();
    for (int o = 64; o > 0; o >>= 1) { if (threadIdx.x < o) red[threadIdx.x] += red[threadIdx.x + o]; __syncthreads(); }
    if (threadIdx.x == 0) {
        float var = red[0] / DD - s_mu * s_mu;
        s_rs = rsqrtf(var + 1e-5f);
    }
    __syncthreads();
    float mu = s_mu, rs = s_rs;
    for (int kp = threadIdx.x; kp < KP; kp += 128) {
        int d0 = kp * 2, d1 = d0 + 1;
        float x0 = (d0 < DD) ? (xr[d0] - mu) * rs * lng[d0] + lnb[d0] : 0.f;
        float x1 = (d1 < DD) ? (xr[d1] - mu) * rs * lng[d1] + lnb[d1] : 0.f;
        g_h16[(size_t)row * KP + kp] = pack_split(x0, x1);
    }
}

// ---------------- W GEMM, fp16 3-split m16n8k16 (unchanged from R10) ----------------
__global__ void __launch_bounds__(128) k_wgemm(const float* __restrict__ bias) {
    __shared__ uint2 sA[64 * 20];   // [row][kp0..15], stride 20
    __shared__ uint2 sB[16 * 68];   // [kp][e0..63],   stride 68
    int g  = blockIdx.z;
    int n0 = blockIdx.x * 64;
    int m0 = blockIdx.y * 64;
    int t = threadIdx.x, lane = t & 31, wid = t >> 5;
    int wm = wid >> 1, wn = wid & 1;

    float acc[2][4][4];
#pragma unroll
    for (int i = 0; i < 2; i++)
#pragma unroll
        for (int j = 0; j < 4; j++)
#pragma unroll
            for (int k = 0; k < 4; k++) acc[i][j][k] = 0.f;

    const uint2* Wbase = g_W16 + (size_t)g * KP * DD;

    for (int kc = 0; kc < NKCW; kc++) {
        {
            int row = t >> 1, kb = (t & 1) * 8;
            const uint2* src = g_h16 + (size_t)(m0 + row) * KP + kc * 16 + kb;
            uint2* dst = sA + row * 20 + kb;
            *(uint4*)(dst)     = *(const uint4*)(src);
            *(uint4*)(dst + 2) = *(const uint4*)(src + 2);
            *(uint4*)(dst + 4) = *(const uint4*)(src + 4);
            *(uint4*)(dst + 6) = *(const uint4*)(src + 6);
        }
        {
#pragma unroll
            for (int it = 0; it < 8; it++) {
                int i = t + it * 128;
                int kpr = i >> 6, c = i & 63;
                int ge = n0 + c;
                uint2 v = make_uint2(0u, 0u);
                if (ge < DD) v = Wbase[(size_t)(kc * 16 + kpr) * DD + ge];
                sB[kpr * 68 + c] = v;
            }
        }
        __syncthreads();
#pragma unroll
        for (int ts = 0; ts < 2; ts++) {
            int kpf = ts * 8 + (lane & 3);
            unsigned ah[2][4], al[2][4];
#pragma unroll
            for (int mi = 0; mi < 2; mi++) {
                int row = wm * 32 + mi * 16 + (lane >> 2);
                const uint2* Ap = sA + row * 20;
                uint2 x0 = Ap[kpf], x1 = Ap[160 + kpf];
                uint2 x2 = Ap[kpf + 4], x3 = Ap[160 + kpf + 4];
                ah[mi][0] = x0.x; ah[mi][1] = x1.x; ah[mi][2] = x2.x; ah[mi][3] = x3.x;
                al[mi][0] = x0.y; al[mi][1] = x1.y; al[mi][2] = x2.y; al[mi][3] = x3.y;
            }
#pragma unroll
            for (int ni = 0; ni < 4; ni++) {
                int cb = wn * 32 + ni * 8 + (lane >> 2);
                uint2 b0 = sB[kpf * 68 + cb];
                uint2 b1 = sB[(kpf + 4) * 68 + cb];
                unsigned bh[2] = {b0.x, b1.x};
                unsigned bl[2] = {b0.y, b1.y};
#pragma unroll
                for (int mi = 0; mi < 2; mi++) {
                    mma16(acc[mi][ni], ah[mi], bh);
                    mma16(acc[mi][ni], ah[mi], bl);
                    mma16(acc[mi][ni], al[mi], bh);
                }
            }
        }
        __syncthreads();
    }
    const float* bp = bias + g * DD;
#pragma unroll
    for (int mi = 0; mi < 2; mi++) {
        int row0 = m0 + wm * 32 + mi * 16 + (lane >> 2);
        int row1 = row0 + 8;
        int b0r = row0 / SS, s0r = row0 - b0r * SS;
        int b1r = row1 / SS, s1r = row1 - b1r * SS;
        float* o0 = g_pre + (size_t)(s0r * BB + b0r) * NCOL + g;
        float* o1 = g_pre + (size_t)(s1r * BB + b1r) * NCOL + g;
#pragma unroll
        for (int ni = 0; ni < 4; ni++) {
            int e = n0 + wn * 32 + ni * 8 + (lane & 3) * 2;
            if (e < DD) {
                float bv0 = bp[e], bv1 = bp[e + 1];
                o0[(e) * 4]     = acc[mi][ni][0] + bv0;
                o0[(e + 1) * 4] = acc[mi][ni][1] + bv1;
                o1[(e) * 4]     = acc[mi][ni][2] + bv0;
                o1[(e + 1) * 4] = acc[mi][ni][3] + bv1;
            }
        }
    }
}

// ---------------- persistent scan ----------------
#define SB_SZ (KP * 68 * 8)            /* 156672: R hi+lo persistent */
#define SA_SZ (2 * 64 * 36 * 8)        /* 36864:  A dbl buffer, 32 kp chunks */
#define SCAN_SMEM (SB_SZ + SA_SZ)      /* 193536 */

__device__ __forceinline__ void group_barrier(int grp, unsigned target) {
    __threadfence();
    __syncthreads();
    if (threadIdx.x == 0) {
        unsigned arr = atomicAdd(&g_bcnt[grp * 32], 1u);
        if (arr == CBLK - 1u) {
            *((volatile unsigned*)&g_bcnt[grp * 32]) = 0u;
            __threadfence();
            atomicExch(&g_bgen[grp * 32], target);
        } else {
            while (*((volatile unsigned*)&g_bgen[grp * 32]) < target) __nanosleep(32);
            __threadfence();
        }
    }
    __syncthreads();
}

__global__ void __launch_bounds__(256, 1) k_scan() {
    extern __shared__ char smraw[];
    uint2* sB = (uint2*)smraw;                 // [kp][c], stride 68
    uint2* sA = (uint2*)(smraw + SB_SZ);       // 2 x [row][kp0..31], stride 36

    int t = threadIdx.x, lane = t & 31;
    int wid = t >> 5, wm = wid >> 2, wn = wid & 3;
    int cb0 = blockIdx.x * 64;
    int b0  = blockIdx.y * 64;
    int grp = blockIdx.y;

    // fill persistent R tile (hi+lo)
    for (int i = t; i < KP * 64; i += 256) {
        int kp = i >> 6, c = i & 63;
        int gc = cb0 + c;
        uint2 v = make_uint2(0u, 0u);
        if (gc < NCOL) v = g_R16[(size_t)kp * NCOL + gc];
        sB[kp * 68 + c] = v;
    }

    // zero h0 (split/packed) for this b-group (redundant across col-blocks; benign)
    for (int i = t; i < 64 * KP; i += 256) g_h16s[0][(size_t)b0 * KP + i] = make_uint2(0u, 0u);

    float sc[2][2][2], snr[2][2][2], smx[2][2][2];
#pragma unroll
    for (int a = 0; a < 2; a++)
#pragma unroll
        for (int b = 0; b < 2; b++)
#pragma unroll
            for (int c = 0; c < 2; c++) { sc[a][b][c] = 0.f; snr[a][b][c] = 0.f; smx[a][b][c] = 0.f; }

    unsigned target = *((volatile unsigned*)&g_bgen[grp * 32]);
    ++target; group_barrier(grp, target);

    const int ar = t >> 2, akpb = (t & 3) * 8;   // A staging: row, kp base (8 uint2 = 4x16B)
    unsigned sAbase = (unsigned)__cvta_generic_to_shared(sA);

    for (int s = 0; s < SS; s++) {
        const uint2* hsrc = g_h16s[s & 1] + (size_t)(b0 + ar) * KP + akpb;
        uint2*       hn16 = g_h16s[(s & 1) ^ 1];

        float acc[2][2][4];
#pragma unroll
        for (int i = 0; i < 2; i++)
#pragma unroll
            for (int j = 0; j < 2; j++)
#pragma unroll
                for (int k = 0; k < 4; k++) acc[i][j][k] = 0.f;

        // stage chunk 0 into buf 0
        {
            unsigned dst = sAbase + (ar * 36 + akpb) * 8;
#pragma unroll
            for (int j = 0; j < 4; j++) cpasync16(dst + j * 16, hsrc + j * 2);
            cpasync_commit();
            cpasync_wait<0>();
        }
        __syncthreads();

        for (int kc = 0; kc < NKC9; kc++) {
            int buf = kc & 1;
            bool more = (kc + 1 < NKC9);
            if (more) {   // stage next chunk into buf^1 (safe: synced after its last compute)
                unsigned dst = sAbase + ((buf ^ 1) * (64 * 36) + ar * 36 + akpb) * 8;
                const uint2* src = hsrc + (kc + 1) * 32;
#pragma unroll
                for (int j = 0; j < 4; j++) cpasync16(dst + j * 16, src + j * 2);
                cpasync_commit();
            }
            const uint2* Ab = sA + buf * (64 * 36);
            int kpc = kc * 32;
#pragma unroll
            for (int ts = 0; ts < 4; ts++) {
                int kpl = ts * 8 + (lane & 3);
                unsigned ah[2][4], al[2][4];
#pragma unroll
                for (int mi = 0; mi < 2; mi++) {
                    int row = wm * 32 + mi * 16 + (lane >> 2);
                    const uint2* Ap = Ab + row * 36;
                    uint2 x0 = Ap[kpl],       x1 = Ap[288 + kpl];
                    uint2 x2 = Ap[kpl + 4],   x3 = Ap[288 + kpl + 4];
                    ah[mi][0] = x0.x; ah[mi][1] = x1.x; ah[mi][2] = x2.x; ah[mi][3] = x3.x;
                    al[mi][0] = x0.y; al[mi][1] = x1.y; al[mi][2] = x2.y; al[mi][3] = x3.y;
                }
#pragma unroll
                for (int ni = 0; ni < 2; ni++) {
                    int cb = wn * 16 + ni * 8 + (lane >> 2);
                    int kpf = kpc + kpl;
                    uint2 b0v = sB[kpf * 68 + cb];
                    uint2 b1v = sB[(kpf + 4) * 68 + cb];
                    unsigned bh[2] = {b0v.x, b1v.x};
                    unsigned bl[2] = {b0v.y, b1v.y};
#pragma unroll
                    for (int mi = 0; mi < 2; mi++) {
                        mma16(acc[mi][ni], ah[mi], bh);
                        mma16(acc[mi][ni], ah[mi], bl);
                        mma16(acc[mi][ni], al[mi], bh);
                    }
                }
            }
            if (more) cpasync_wait<0>();
            __syncthreads();
        }

        // fused sLSTM epilogue; h_new written back pre-split/packed
#pragma unroll
        for (int mi = 0; mi < 2; mi++) {
            int br = b0 + wm * 32 + mi * 16 + (lane >> 2);
#pragma unroll
            for (int ni = 0; ni < 2; ni++) {
                float d0 = acc[mi][ni][0], d1 = acc[mi][ni][1];
                float d2 = acc[mi][ni][2], d3 = acc[mi][ni][3];
                float p0 = __shfl_xor_sync(0xffffffffu, d0, 1);
                float p1 = __shfl_xor_sync(0xffffffffu, d1, 1);
                float p2 = __shfl_xor_sync(0xffffffffu, d2, 1);
                float p3 = __shfl_xor_sync(0xffffffffu, d3, 1);
                if ((lane & 1) == 0) {
                    int c = cb0 + wn * 16 + ni * 8 + (lane & 3) * 2;
                    bool valid = (c < NCOL);
                    int e = c >> 2;
                    float hvv[2];
#pragma unroll
                    for (int rr = 0; rr < 2; rr++) {
                        int bb = br + rr * 8;
                        float4 pr = make_float4(0.f, 0.f, 0.f, 0.f);
                        if (valid) pr = *(const float4*)(g_pre + (size_t)(s * BB + bb) * NCOL + c);
                        float it = (rr ? d2 : d0) + pr.x;
                        float ft = (rr ? d3 : d1) + pr.y;
                        float zt = (rr ? p2 : p0) + pr.z;
                        float ot = (rr ? p3 : p1) + pr.w;
                        float mo = smx[mi][ni][rr];
                        float mn = fmaxf(ft + mo, it);
                        float iv = expf(it - mn);
                        float fv = expf(ft + mo - mn);
                        float cn = fv * sc[mi][ni][rr] + iv * tanhf(zt);
                        float nn = fv * snr[mi][ni][rr] + iv;
                        float sg = 1.f / (1.f + expf(-ot));
                        float hv = sg * cn / fmaxf(nn, 1e-6f);
                        sc[mi][ni][rr] = cn; snr[mi][ni][rr] = nn; smx[mi][ni][rr] = mn;
                        hvv[rr] = valid ? hv : 0.f;
                        if (valid) g_x[(size_t)(bb * SS + s) * DD + e] += hv;
                    }
                    // pack (e, e+1) pairs: lane with (lane&3)==0 holds e, partner lane^2 holds e+1
                    float o0 = __shfl_xor_sync(0x55555555u, hvv[0], 2);
                    float o1 = __shfl_xor_sync(0x55555555u, hvv[1], 2);
                    if ((lane & 3) == 0) {
                        int kp = c >> 3;    // e/2, e even on these lanes
                        hn16[(size_t)br * KP + kp]       = pack_split(hvv[0], o0);
                        hn16[(size_t)(br + 8) * KP + kp] = pack_split(hvv[1], o1);
                    }
                }
            }
        }
        ++target; group_barrier(grp, target);
    }
}

// ---------------- batchnorm statistics ----------------
__global__ void k_bnstats() {
    int d = blockIdx.x;
    __shared__ float r1[256], r2[256];
    float s1 = 0.f, s2 = 0.f;
    for (int r = threadIdx.x; r < ROWS; r += 256) {
        float v = g_x[(size_t)r * DD + d];
        s1 += v; s2 += v * v;
    }
    r1[threadIdx.x] = s1; r2[threadIdx.x] = s2; __syncthreads();
    for (int o = 128; o > 0; o >>= 1) {
        if (threadIdx.x < o) { r1[threadIdx.x] += r1[threadIdx.x + o]; r2[threadIdx.x] += r2[threadIdx.x + o]; }
        __syncthreads();
    }
    if (threadIdx.x == 0) {
        float mu = r1[0] / (float)ROWS;
        float var = r2[0] / (float)ROWS - mu * mu;
        g_mean[d] = mu;
        g_rstd[d] = rsqrtf(var + 1e-5f);
    }
}

// ---------------- final projection ----------------
__global__ void k_final(const float* __restrict__ w6, const float* __restrict__ b6,
                        const float* __restrict__ bng, const float* __restrict__ bnb,
                        float* __restrict__ out) {
    int bp = blockIdx.x;
    int b = bp / PP, p = bp % PP;
    __shared__ float r0[128], r1[128];
    float a0 = 0.f, a1 = 0.f;
    for (int i = threadIdx.x; i < OUTIN; i += 128) {
        int flat = p * OUTIN + i;
        int d = flat / SS, s = flat % SS;
        float v = g_x[(size_t)(b * SS + s) * DD + d];
        float xn = (v - g_mean[d]) * g_rstd[d] * bng[d] + bnb[d];
        a0 += xn * w6[i * 2 + 0];
        a1 += xn * w6[i * 2 + 1];
    }
    r0[threadIdx.x] = a0; r1[threadIdx.x] = a1; __syncthreads();
    for (int o = 64; o > 0; o >>= 1) {
        if (threadIdx.x < o) { r0[threadIdx.x] += r0[threadIdx.x + o]; r1[threadIdx.x] += r1[threadIdx.x + o]; }
        __syncthreads();
    }
    if (threadIdx.x == 0) {
        out[bp * 2 + 0] = tanhf(r0[0] + b6[0]);
        out[bp * 2 + 1] = tanhf(r1[0] + b6[1]);
    }
}

// ---------------- launch ----------------
extern "C" void kernel_launch(void* const* d_in, const int* in_sizes, int n_in,
                              void* d_out, int out_size) {
    const float* inp = (const float*)d_in[0];
    const float* Wg  = (const float*)d_in[1];
    const float* Rg  = (const float*)d_in[2];
    const float* bgp = (const float*)d_in[3];
    const float* lng = (const float*)d_in[4];
    const float* lnb = (const float*)d_in[5];
    const float* bng = (const float*)d_in[6];
    const float* bnb = (const float*)d_in[7];
    const float* w6  = (const float*)d_in[8];
    const float* b6  = (const float*)d_in[9];
    float* out = (float*)d_out;

    cudaFuncSetAttribute(k_scan, cudaFuncAttributeMaxDynamicSharedMemorySize, SCAN_SMEM);

    const int NWQ = 4 * KP * DD;
    k_reshape<<<(ROWS * DD + 255) / 256, 256>>>(inp);
    for (int l = 0; l < NBL; l++) {
        k_convW<<<(NWQ + 255) / 256, 256>>>(Wg + (size_t)l * 4 * DD * DD);
        k_convR<<<(KP * NCOL + 255) / 256, 256>>>(Rg + (size_t)l * 4 * DD * DD);
        k_layernorm<<<ROWS, 128>>>(lng + l * DD, lnb + l * DD);
        k_wgemm<<<dim3(9, 160, 4), 128>>>(bgp + (size_t)l * 4 * DD);
        k_scan<<<dim3(CBLK, BBLK), 256, SCAN_SMEM>>>();
    }
    k_bnstats<<<DD, 256>>>();
    k_final<<<BB * PP, 128>>>(w6, b6, bng, bnb, out);
}